// round 12
// baseline (speedup 1.0000x reference)
#include <cuda_runtime.h>
#include <cuda_fp16.h>
#include <cuda_pipeline.h>
#include <mma.h>
#include <math.h>
#include <cstdint>

using namespace nvcuda;

// ---------------- problem constants ----------------
#define NTOK   65536
#define BATCH  8
#define SEQ    8192
#define DMODEL 512
#define NHEAD  8
#define NKV    2
#define DHEAD  64
#define MFEAT  64
#define DFF    2048
#define NCLS   2
#define EPSV   1e-6f
#define KCHUNK 32

// ---------------- scratch ----------------
__device__ float  g_x   [NTOK * DMODEL];
__device__ __half g_h   [NTOK * DMODEL];
__device__ __half g_pq  [NTOK * DMODEL];          // [NTOK,512] head-major cols
__device__ __half g_pk  [NTOK * NKV * MFEAT];     // [NTOK,128]
__device__ __half g_v   [NTOK * NKV * DHEAD];     // [NTOK,128]
__device__ __half g_att [NTOK * DMODEL];
__device__ __half g_gu  [NTOK * DFF];
__device__ float  g_kvp [16 * KCHUNK * 64 * 65];
__device__ float  g_xm  [BATCH * DMODEL];
// converted fp16 weights, row-major [K, N]
__device__ __half g_WqkvH[DMODEL * 768];
__device__ __half g_WphiH[DHEAD * MFEAT];
__device__ __half g_WoH  [DMODEL * DMODEL];
__device__ __half g_WguH [DMODEL * (2*DFF)];
__device__ __half g_WdH  [DFF * DMODEL];

struct alignas(8) half4 { __half2 a, b; };
__device__ __forceinline__ half4 f4_to_h4(float4 v) {
    half4 r; r.a = __floats2half2_rn(v.x, v.y); r.b = __floats2half2_rn(v.z, v.w); return r;
}

// ---------------- single merged weight conversion ----------------
#define CQKV 393216
#define CGU  2097152
#define CPHI 4096
#define CWO  262144
#define CWD  1048576
#define CTOT (CQKV + CGU + CPHI + CWO + CWD)

__global__ void conv_all(const float* __restrict__ Wq, const float* __restrict__ Wk,
                         const float* __restrict__ Wv, const float* __restrict__ Wg,
                         const float* __restrict__ Wu, const float* __restrict__ Wphi,
                         const float* __restrict__ Wo, const float* __restrict__ Wd,
                         __half* __restrict__ WqkvH, __half* __restrict__ WguH,
                         __half* __restrict__ WphiH, __half* __restrict__ WoH,
                         __half* __restrict__ WdH)
{
    int idx = blockIdx.x * 256 + threadIdx.x;
    if (idx < CQKV) {
        int r = idx / 768, c = idx % 768;
        float v = (c < 512) ? Wq[r * 512 + c]
                            : (c < 640 ? Wk[r * 128 + c - 512] : Wv[r * 128 + c - 640]);
        WqkvH[idx] = __float2half(v);
        return;
    }
    idx -= CQKV;
    if (idx < CGU) {
        int r = idx >> 12, c = idx & 4095;
        int j = c >> 1;
        float v = (c & 1) ? Wu[r * DFF + j] : Wg[r * DFF + j];
        WguH[idx] = __float2half(v);
        return;
    }
    idx -= CGU;
    if (idx < CPHI) { WphiH[idx] = __float2half(Wphi[idx]); return; }
    idx -= CPHI;
    if (idx < CWO)  { WoH[idx]   = __float2half(Wo[idx]);   return; }
    idx -= CWO;
    if (idx < CWD)  { WdH[idx]   = __float2half(Wd[idx]);   return; }
}

// ---------------- fp16 WMMA GEMM: 128 thr, 64x64 warp tile, 4 stages, 2 blk/SM ------
#define EPI_QKVPHI 0   // fused: q/k cols -> phi -> pq/pk ; v cols passthrough
#define EPI_RES    2
#define EPI_SWIGLU 3
#define STAGES 4
#define NTHR   128

template<int BN, int EPI>
__global__ __launch_bounds__(NTHR, 2) void gemm_h(
    const __half* __restrict__ A, const __half* __restrict__ B,
    void* __restrict__ Cout, const float* __restrict__ X,
    const __half* __restrict__ WphiG,
    __half* __restrict__ pkOut, __half* __restrict__ vOut,
    int M, int K, int Nc)
{
    constexpr int BM = 128, BK = 32;
    constexpr int LDA_S = BK + 8;
    constexpr int LDB_S = BN + 8;
    constexpr int LDC_S = BN + 4;
    constexpr int MI = 4;
    constexpr int NJ = BN / 32;
    constexpr int A_ELE = BM * LDA_S;
    constexpr int B_ELE = BK * LDB_S;
    constexpr int STG_ELE = A_ELE + B_ELE;

    extern __shared__ __align__(16) char smem_raw[];
    __half* stg = (__half*)smem_raw;

    const int tid  = threadIdx.x;
    const int bm   = blockIdx.y * BM;
    const int bn   = blockIdx.x * BN;
    const int warp = tid >> 5;
    const int wm   = (warp & 1) * 64;
    const int wn   = (warp >> 1) * (BN / 2);

    wmma::fragment<wmma::accumulator, 16, 16, 16, float> c[MI][NJ];
#pragma unroll
    for (int i = 0; i < MI; i++)
#pragma unroll
        for (int j = 0; j < NJ; j++) wmma::fill_fragment(c[i][j], 0.0f);

    const int nK = K / BK;

    auto load_stage = [&](int kt, int s) {
        __half* As = stg + s * STG_ELE;
        __half* Bs = As + A_ELE;
#pragma unroll
        for (int i = 0; i < 4; i++) {
            int idx = tid + i * NTHR;
            int r  = idx >> 2;
            int cc = (idx & 3) * 8;
            __pipeline_memcpy_async(&As[r * LDA_S + cc],
                                    &A[(size_t)(bm + r) * K + kt + cc], 16);
        }
        constexpr int CH = BN / 8;
        constexpr int NB = (BK * CH) / NTHR;
#pragma unroll
        for (int i = 0; i < NB; i++) {
            int idx = tid + i * NTHR;
            int r  = idx / CH;
            int cc = (idx % CH) * 8;
            __pipeline_memcpy_async(&Bs[r * LDB_S + cc],
                                    &B[(size_t)(kt + r) * Nc + bn + cc], 16);
        }
    };

#pragma unroll
    for (int s = 0; s < STAGES - 1; s++) {
        if (s < nK) load_stage(s * BK, s);
        __pipeline_commit();
    }

    for (int kt_i = 0; kt_i < nK; kt_i++) {
        __pipeline_wait_prior(STAGES - 2);
        __syncthreads();
        int ldk = kt_i + STAGES - 1;
        if (ldk < nK) load_stage(ldk * BK, ldk % STAGES);
        __pipeline_commit();

        int s = kt_i % STAGES;
        __half* As = stg + s * STG_ELE;
        __half* Bs = As + A_ELE;
#pragma unroll
        for (int kk = 0; kk < BK; kk += 16) {
            wmma::fragment<wmma::matrix_a, 16, 16, 16, __half, wmma::row_major> a[MI];
            wmma::fragment<wmma::matrix_b, 16, 16, 16, __half, wmma::row_major> b[NJ];
#pragma unroll
            for (int i = 0; i < MI; i++)
                wmma::load_matrix_sync(a[i], &As[(wm + i * 16) * LDA_S + kk], LDA_S);
#pragma unroll
            for (int j = 0; j < NJ; j++)
                wmma::load_matrix_sync(b[j], &Bs[kk * LDB_S + wn + j * 16], LDB_S);
#pragma unroll
            for (int i = 0; i < MI; i++)
#pragma unroll
                for (int j = 0; j < NJ; j++)
                    wmma::mma_sync(c[i][j], a[i], b[j], c[i][j]);
        }
    }

    // ---- epilogues ----
    if (EPI == EPI_RES) {
#pragma unroll
        for (int i = 0; i < MI; i++) {
#pragma unroll
            for (int j = 0; j < NJ; j++) {
                int grow = bm + wm + i * 16;
                int gcol = bn + wn + j * 16;
                wmma::fragment<wmma::accumulator, 16, 16, 16, float> xf;
                wmma::load_matrix_sync(xf, X + (size_t)grow * Nc + gcol, Nc,
                                       wmma::mem_row_major);
#pragma unroll
                for (int t = 0; t < xf.num_elements; t++)
                    xf.x[t] += c[i][j].x[t];
                wmma::store_matrix_sync((float*)Cout + (size_t)grow * Nc + gcol, xf, Nc,
                                        wmma::mem_row_major);
            }
        }
    } else if (EPI == EPI_SWIGLU) {
        __syncthreads();
        float* Cs = (float*)smem_raw;
        constexpr int F4R = BN / 4;
        constexpr int NIT = (64 * F4R) / NTHR;
#pragma unroll
        for (int hrow = 0; hrow < 2; hrow++) {
            __syncthreads();
            if ((wm >> 6) == hrow) {
#pragma unroll
                for (int i = 0; i < MI; i++)
#pragma unroll
                    for (int j = 0; j < NJ; j++)
                        wmma::store_matrix_sync(&Cs[((wm & 63) + i * 16) * LDC_S + wn + j * 16],
                                                c[i][j], LDC_S, wmma::mem_row_major);
            }
            __syncthreads();
#pragma unroll
            for (int i = 0; i < NIT; i++) {
                int e  = tid + i * NTHR;
                int r  = e / F4R;
                int cc = (e % F4R) * 4;
                float4 vv = *(float4*)&Cs[r * LDC_S + cc];
                int grow = bm + hrow * 64 + r;
                float s0 = vv.x / (1.0f + expf(-vv.x)) * vv.y;
                float s1 = vv.z / (1.0f + expf(-vv.z)) * vv.w;
                int jo = (bn + cc) >> 1;
                *(__half2*)&((__half*)Cout)[(size_t)grow * (Nc >> 1) + jo] =
                    __floats2half2_rn(s0, s1);
            }
        }
    } else {
        // EPI_QKVPHI. Tile types by bn: <512 q (2 heads), ==512 k (2 kv heads), ==640 v.
        if (bn == 640) {
            // v passthrough: fragment-direct fp16 store
#pragma unroll
            for (int i = 0; i < MI; i++) {
#pragma unroll
                for (int j = 0; j < NJ; j++) {
                    wmma::fragment<wmma::accumulator, 16, 16, 16, __half> ch;
#pragma unroll
                    for (int t = 0; t < ch.num_elements; t++)
                        ch.x[t] = __float2half(c[i][j].x[t]);
                    int grow = bm + wm + i * 16;
                    int c0 = wn + j * 16;
                    wmma::store_matrix_sync(vOut + (size_t)grow * 128 + c0, ch, 128,
                                            wmma::mem_row_major);
                }
            }
        } else {
            // stage C (fp16) + Wphi, then per-head 64x64 phi GEMM
            __syncthreads();
            constexpr int LDC_H = 136;
            constexpr int LDW   = 72;
            __half* Cs = (__half*)smem_raw;                 // 128 x 136
            __half* Wp = (__half*)smem_raw + BM * LDC_H;    // 64 x 72
#pragma unroll
            for (int i = 0; i < MI; i++) {
#pragma unroll
                for (int j = 0; j < NJ; j++) {
                    wmma::fragment<wmma::accumulator, 16, 16, 16, __half> ch;
#pragma unroll
                    for (int t = 0; t < ch.num_elements; t++)
                        ch.x[t] = __float2half(c[i][j].x[t]);
                    wmma::store_matrix_sync(&Cs[(wm + i * 16) * LDC_H + wn + j * 16],
                                            ch, LDC_H, wmma::mem_row_major);
                }
            }
#pragma unroll
            for (int i = 0; i < 4; i++) {
                int e = tid + i * NTHR;            // 512 chunks of 8 halves
                int r = e >> 3, c8 = (e & 7) * 8;
                *(uint4*)&Wp[r * LDW + c8] = *(const uint4*)&WphiG[r * 64 + c8];
            }
            __syncthreads();

            const int hh = warp >> 1, mhalf = warp & 1;
            wmma::fragment<wmma::accumulator, 16, 16, 16, float> c2[4][4];
#pragma unroll
            for (int i = 0; i < 4; i++)
#pragma unroll
                for (int j = 0; j < 4; j++) wmma::fill_fragment(c2[i][j], 0.0f);
#pragma unroll
            for (int kk = 0; kk < 64; kk += 16) {
                wmma::fragment<wmma::matrix_a, 16, 16, 16, __half, wmma::row_major> a2[4];
                wmma::fragment<wmma::matrix_b, 16, 16, 16, __half, wmma::row_major> b2[4];
#pragma unroll
                for (int i = 0; i < 4; i++)
                    wmma::load_matrix_sync(a2[i],
                        &Cs[(mhalf * 64 + i * 16) * LDC_H + hh * 64 + kk], LDC_H);
#pragma unroll
                for (int j = 0; j < 4; j++)
                    wmma::load_matrix_sync(b2[j], &Wp[kk * LDW + j * 16], LDW);
#pragma unroll
                for (int i = 0; i < 4; i++)
#pragma unroll
                    for (int j = 0; j < 4; j++)
                        wmma::mma_sync(c2[i][j], a2[i], b2[j], c2[i][j]);
            }
#pragma unroll
            for (int i = 0; i < 4; i++) {
#pragma unroll
                for (int j = 0; j < 4; j++) {
                    wmma::fragment<wmma::accumulator, 16, 16, 16, __half> ph;
#pragma unroll
                    for (int t = 0; t < ph.num_elements; t++)
                        ph.x[t] = __float2half(expf(-fabsf(c2[i][j].x[t])));
                    int grow = bm + mhalf * 64 + i * 16;
                    if (bn < 512) {
                        int headg = (bn >> 6) + hh;
                        wmma::store_matrix_sync(
                            (__half*)Cout + (size_t)grow * 512 + headg * 64 + j * 16,
                            ph, 512, wmma::mem_row_major);
                    } else {
                        wmma::store_matrix_sync(
                            pkOut + (size_t)grow * 128 + hh * 64 + j * 16,
                            ph, 128, wmma::mem_row_major);
                    }
                }
            }
        }
    }
}

// ---------------- gather + rmsnorm ----------------
__global__ __launch_bounds__(128) void gather_rmsnorm_kernel(
    const int* __restrict__ ids, const float* __restrict__ emb,
    const float* __restrict__ xin, const float* __restrict__ g,
    float* __restrict__ xout, __half* __restrict__ h)
{
    int token = blockIdx.x;
    const float* src = ids ? (emb + (size_t)ids[token] * DMODEL)
                           : (xin + (size_t)token * DMODEL);
    int c = threadIdx.x * 4;
    float4 v = *(const float4*)&src[c];
    float ss = v.x * v.x + v.y * v.y + v.z * v.z + v.w * v.w;
#pragma unroll
    for (int off = 16; off > 0; off >>= 1) ss += __shfl_xor_sync(0xffffffffu, ss, off);
    __shared__ float sred[4];
    int warp = threadIdx.x >> 5, lane = threadIdx.x & 31;
    if (lane == 0) sred[warp] = ss;
    __syncthreads();
    float tot = sred[0] + sred[1] + sred[2] + sred[3];
    float scale = rsqrtf(tot * (1.0f / DMODEL) + EPSV);
    float4 gv = *(const float4*)&g[c];
    float4 o;
    o.x = v.x * scale * gv.x; o.y = v.y * scale * gv.y;
    o.z = v.z * scale * gv.z; o.w = v.w * scale * gv.w;
    if (xout) *(float4*)&xout[(size_t)token * DMODEL + c] = v;
    *(half4*)&h[(size_t)token * DMODEL + c] = f4_to_h4(o);
}

// ---------------- kv state partials (32 chunks) ----------------
__global__ __launch_bounds__(256) void kv_partial_kernel(
    const __half* __restrict__ pk, const __half* __restrict__ v, float* __restrict__ kvp)
{
    int pair = blockIdx.x, chunk = blockIdx.y;
    int b = pair >> 1, kh = pair & 1;
    int tid = threadIdx.x;
    int ti = tid >> 4, tj = tid & 15;
    float acc[4][4], zacc[4];
#pragma unroll
    for (int a = 0; a < 4; a++) { zacc[a] = 0.f;
#pragma unroll
        for (int bb = 0; bb < 4; bb++) acc[a][bb] = 0.f; }
    __shared__ float spk[16][64], sv[16][64];
    const int CL = SEQ / KCHUNK;     // 256
    int s0 = chunk * CL;
    for (int sb = 0; sb < CL; sb += 16) {
#pragma unroll
        for (int j = 0; j < 4; j++) {
            int idx = tid + j * 256;
            int t = idx >> 6, lane = idx & 63;
            int token = b * SEQ + s0 + sb + t;
            size_t base = ((size_t)token * NKV + kh) * 64 + lane;
            spk[t][lane] = __half2float(pk[base]);
            sv[t][lane]  = __half2float(v[base]);
        }
        __syncthreads();
#pragma unroll
        for (int t = 0; t < 16; t++) {
            float pm[4], vd[4];
#pragma unroll
            for (int mm = 0; mm < 4; mm++) pm[mm] = spk[t][ti * 4 + mm];
#pragma unroll
            for (int dd = 0; dd < 4; dd++) vd[dd] = sv[t][tj * 4 + dd];
#pragma unroll
            for (int mm = 0; mm < 4; mm++) {
#pragma unroll
                for (int dd = 0; dd < 4; dd++) acc[mm][dd] = fmaf(pm[mm], vd[dd], acc[mm][dd]);
                if (tj == 0) zacc[mm] += pm[mm];
            }
        }
        __syncthreads();
    }
    int pc = pair * KCHUNK + chunk;
#pragma unroll
    for (int mm = 0; mm < 4; mm++) {
#pragma unroll
        for (int dd = 0; dd < 4; dd++)
            kvp[(size_t)pc * 4160 + (ti * 4 + mm) * 65 + tj * 4 + dd] = acc[mm][dd];
        if (tj == 0) kvp[(size_t)pc * 4160 + (ti * 4 + mm) * 65 + 64] = zacc[mm];
    }
}

// ---------------- num/den with fused 32-chunk reduction ----------------
__global__ __launch_bounds__(256) void numden_kernel(
    const __half* __restrict__ pq, const float* __restrict__ kvp, __half* __restrict__ att)
{
    int b = blockIdx.y;
    __shared__ float skv[2 * 64 * 65];
    __shared__ float spq[4][64];
    for (int idx = threadIdx.x; idx < 8320; idx += 256) {
        int kh = idx / 4160, off = idx % 4160;
        const float* src = kvp + (size_t)((b * 2 + kh) * KCHUNK) * 4160 + off;
        float s = 0.f;
#pragma unroll
        for (int c = 0; c < KCHUNK; c++) s += src[c * 4160];
        skv[idx] = s;
    }
    __syncthreads();
    int group = threadIdx.x >> 6, lane = threadIdx.x & 63;
    int base = blockIdx.x * 128;
    for (int it = 0; it < 32; it++) {
        int th = base + it * 4 + group;
        size_t row = ((size_t)b * (SEQ * NHEAD) + th) * 64;
        spq[group][lane] = __half2float(pq[row + lane]);
        __syncthreads();
        int h = th & 7;
        const float* kvh = &skv[(h >> 2) * 4160];
        float num = 0.f, den = 0.f;
#pragma unroll
        for (int m = 0; m < 64; m++) {
            float p = spq[group][m];
            num = fmaf(p, kvh[m * 65 + lane], num);
            den = fmaf(p, kvh[m * 65 + 64], den);
        }
        att[row + lane] = __float2half(num / (den + EPSV));
        __syncthreads();
    }
}

// ---------------- pool + head ----------------
__global__ __launch_bounds__(256) void pool_kernel(
    const float* __restrict__ x, float* __restrict__ xm)
{
    int b = blockIdx.y;
    int c = blockIdx.x * 64 + (threadIdx.x & 63);
    int part = threadIdx.x >> 6;
    float s = 0.f;
    for (int t = part; t < SEQ; t += 4)
        s += x[((size_t)b * SEQ + t) * DMODEL + c];
    __shared__ float red[4][64];
    red[part][threadIdx.x & 63] = s;
    __syncthreads();
    if (part == 0) {
        int l = threadIdx.x & 63;
        xm[b * DMODEL + c] = red[0][l] + red[1][l] + red[2][l] + red[3][l];
    }
}

__global__ __launch_bounds__(512) void head_kernel(
    const float* __restrict__ xm, const float* __restrict__ Wc,
    const float* __restrict__ bc, float* __restrict__ out)
{
    int warp = threadIdx.x >> 5, lane = threadIdx.x & 31;
    int b = warp >> 1, cls = warp & 1;
    float s = 0.f;
    for (int d = lane; d < DMODEL; d += 32)
        s += xm[b * DMODEL + d] * Wc[d * NCLS + cls];
#pragma unroll
    for (int off = 16; off > 0; off >>= 1) s += __shfl_xor_sync(0xffffffffu, s, off);
    if (lane == 0) out[b * NCLS + cls] = s * (1.0f / SEQ) + bc[cls];
}

// ---------------- launch ----------------
#define SMEM_BN128_V (STAGES * (128 * 40 + 32 * 136) * 2)   // 75776

extern "C" void kernel_launch(void* const* d_in, const int* in_sizes, int n_in,
                              void* d_out, int out_size)
{
    (void)in_sizes; (void)n_in; (void)out_size;
    const int*   ids  = (const int*)  d_in[0];
    const float* emb  = (const float*)d_in[1];
    const float* Wq   = (const float*)d_in[2];
    const float* Wk   = (const float*)d_in[3];
    const float* Wv   = (const float*)d_in[4];
    const float* Wphi = (const float*)d_in[5];
    const float* Wo   = (const float*)d_in[6];
    const float* g1   = (const float*)d_in[7];
    const float* g2   = (const float*)d_in[8];
    const float* Wg   = (const float*)d_in[9];
    const float* Wu   = (const float*)d_in[10];
    const float* Wd   = (const float*)d_in[11];
    const float* Wc   = (const float*)d_in[12];
    const float* bc   = (const float*)d_in[13];
    float* out = (float*)d_out;

    float *x, *kvp, *xm;
    __half *h, *pq, *pk, *v, *att, *gu;
    __half *WqkvH, *WphiH, *WoH, *WguH, *WdH;
    cudaGetSymbolAddress((void**)&x,    g_x);
    cudaGetSymbolAddress((void**)&h,    g_h);
    cudaGetSymbolAddress((void**)&pq,   g_pq);
    cudaGetSymbolAddress((void**)&pk,   g_pk);
    cudaGetSymbolAddress((void**)&v,    g_v);
    cudaGetSymbolAddress((void**)&att,  g_att);
    cudaGetSymbolAddress((void**)&gu,   g_gu);
    cudaGetSymbolAddress((void**)&kvp,  g_kvp);
    cudaGetSymbolAddress((void**)&xm,   g_xm);
    cudaGetSymbolAddress((void**)&WqkvH, g_WqkvH);
    cudaGetSymbolAddress((void**)&WphiH, g_WphiH);
    cudaGetSymbolAddress((void**)&WoH,   g_WoH);
    cudaGetSymbolAddress((void**)&WguH,  g_WguH);
    cudaGetSymbolAddress((void**)&WdH,   g_WdH);

    cudaFuncSetAttribute(gemm_h<128, EPI_QKVPHI>, cudaFuncAttributeMaxDynamicSharedMemorySize, SMEM_BN128_V);
    cudaFuncSetAttribute(gemm_h<128, EPI_RES>,    cudaFuncAttributeMaxDynamicSharedMemorySize, SMEM_BN128_V);
    cudaFuncSetAttribute(gemm_h<128, EPI_SWIGLU>, cudaFuncAttributeMaxDynamicSharedMemorySize, SMEM_BN128_V);

    // 1. merged weight conversion
    conv_all<<<(CTOT + 255) / 256, 256>>>(Wq, Wk, Wv, Wg, Wu, Wphi, Wo, Wd,
                                          WqkvH, WguH, WphiH, WoH, WdH);

    // 2. embedding gather + rmsnorm
    gather_rmsnorm_kernel<<<NTOK, 128>>>(ids, emb, nullptr, g1, x, h);

    // 3. fused qkv projection + phi feature map (+ v passthrough)
    {
        dim3 grid(768 / 128, NTOK / 128);
        gemm_h<128, EPI_QKVPHI><<<grid, NTHR, SMEM_BN128_V>>>(
            h, WqkvH, pq, nullptr, WphiH, pk, v, NTOK, DMODEL, 768);
    }

    // 4. global kv state partials
    {
        dim3 gp(BATCH * NKV, KCHUNK);
        kv_partial_kernel<<<gp, 256>>>(pk, v, kvp);
    }

    // 5. num/den (fused chunk reduction) -> attn
    {
        dim3 gn(SEQ * NHEAD / 128, BATCH);
        numden_kernel<<<gn, 256>>>(pq, kvp, att);
    }

    // 6. output projection + residual   [profiled launch -s 5 -c 1]
    {
        dim3 grid(DMODEL / 128, NTOK / 128);
        gemm_h<128, EPI_RES><<<grid, NTHR, SMEM_BN128_V>>>(
            att, WoH, x, x, nullptr, nullptr, nullptr, NTOK, DMODEL, DMODEL);
    }

    // 7. pre-FFN rmsnorm
    gather_rmsnorm_kernel<<<NTOK, 128>>>(nullptr, nullptr, x, g2, nullptr, h);

    // 8. fused SwiGLU up
    {
        dim3 grid(4096 / 128, NTOK / 128);
        gemm_h<128, EPI_SWIGLU><<<grid, NTHR, SMEM_BN128_V>>>(
            h, WguH, gu, nullptr, nullptr, nullptr, nullptr, NTOK, DMODEL, 4096);
    }
    // 9. down proj + residual
    {
        dim3 grid(DMODEL / 128, NTOK / 128);
        gemm_h<128, EPI_RES><<<grid, NTHR, SMEM_BN128_V>>>(
            gu, WdH, x, x, nullptr, nullptr, nullptr, NTOK, DFF, DMODEL);
    }

    // 10. mean pool + head
    {
        dim3 gpool(DMODEL / 64, BATCH);
        pool_kernel<<<gpool, 256>>>(x, xm);
    }
    head_kernel<<<1, 512>>>(xm, Wc, bc, out);
}

// round 13
// speedup vs baseline: 1.1451x; 1.1451x over previous
#include <cuda_runtime.h>
#include <cuda_fp16.h>
#include <cuda_pipeline.h>
#include <mma.h>
#include <math.h>
#include <cstdint>

using namespace nvcuda;

// ---------------- problem constants ----------------
#define NTOK   65536
#define BATCH  8
#define SEQ    8192
#define DMODEL 512
#define NHEAD  8
#define NKV    2
#define DHEAD  64
#define MFEAT  64
#define DFF    2048
#define NCLS   2
#define EPSV   1e-6f
#define KCHUNK 32

// ---------------- scratch ----------------
__device__ float  g_x   [NTOK * DMODEL];
__device__ __half g_h   [NTOK * DMODEL];
__device__ __half g_qkv [NTOK * (DMODEL + 2*128)];   // q | k | v contiguous blocks
__device__ __half g_pqk [NTOK * (NHEAD + NKV) * MFEAT];  // pq rows then pk rows
__device__ __half g_att [NTOK * DMODEL];
__device__ __half g_gu  [NTOK * DFF];
__device__ float  g_kvp [16 * KCHUNK * 64 * 65];
__device__ float  g_kv  [16 * 64 * 65];
__device__ float  g_xm  [BATCH * DMODEL];
// converted fp16 weights, row-major [K, N]
__device__ __half g_WqkvH[DMODEL * 768];
__device__ __half g_WphiH[DHEAD * MFEAT];
__device__ __half g_WoH  [DMODEL * DMODEL];
__device__ __half g_WguH [DMODEL * (2*DFF)];   // interleaved g,u columns
__device__ __half g_WdH  [DFF * DMODEL];

struct alignas(8) half4 { __half2 a, b; };
__device__ __forceinline__ half4 f4_to_h4(float4 v) {
    half4 r; r.a = __floats2half2_rn(v.x, v.y); r.b = __floats2half2_rn(v.z, v.w); return r;
}

// ---------------- single merged weight conversion ----------------
#define CQKV 393216
#define CGU  2097152
#define CPHI 4096
#define CWO  262144
#define CWD  1048576
#define CTOT (CQKV + CGU + CPHI + CWO + CWD)

__global__ void conv_all(const float* __restrict__ Wq, const float* __restrict__ Wk,
                         const float* __restrict__ Wv, const float* __restrict__ Wg,
                         const float* __restrict__ Wu, const float* __restrict__ Wphi,
                         const float* __restrict__ Wo, const float* __restrict__ Wd,
                         __half* __restrict__ WqkvH, __half* __restrict__ WguH,
                         __half* __restrict__ WphiH, __half* __restrict__ WoH,
                         __half* __restrict__ WdH)
{
    int idx = blockIdx.x * 256 + threadIdx.x;
    if (idx < CQKV) {
        int r = idx / 768, c = idx % 768;
        float v = (c < 512) ? Wq[r * 512 + c]
                            : (c < 640 ? Wk[r * 128 + c - 512] : Wv[r * 128 + c - 640]);
        WqkvH[idx] = __float2half(v);
        return;
    }
    idx -= CQKV;
    if (idx < CGU) {
        int r = idx >> 12, c = idx & 4095;
        int j = c >> 1;
        float v = (c & 1) ? Wu[r * DFF + j] : Wg[r * DFF + j];
        WguH[idx] = __float2half(v);
        return;
    }
    idx -= CGU;
    if (idx < CPHI) { WphiH[idx] = __float2half(Wphi[idx]); return; }
    idx -= CPHI;
    if (idx < CWO)  { WoH[idx]   = __float2half(Wo[idx]);   return; }
    idx -= CWO;
    if (idx < CWD)  { WdH[idx]   = __float2half(Wd[idx]);   return; }
}

// ---------------- fp16 WMMA GEMM: 128 thr, 64x64 warp tile, 4 stages ----------------
#define EPI_QKV    0
#define EPI_EXPABS 1
#define EPI_RES    2
#define EPI_SWIGLU 3
#define STAGES 4
#define NTHR   128

template<int BN, int EPI>
__global__ __launch_bounds__(NTHR, 3) void gemm_h(
    const __half* __restrict__ A, const __half* __restrict__ B,
    void* __restrict__ Cout, const float* __restrict__ X,
    int M, int K, int Nc)
{
    constexpr int BM = 128, BK = 32;
    constexpr int LDA_S = BK + 8;
    constexpr int LDB_S = BN + 8;
    constexpr int LDC_S = BN + 4;
    constexpr int MI = 4;               // 64/16 m-frags per warp
    constexpr int NJ = BN / 32;         // warp n-tile = BN/2
    constexpr int A_ELE = BM * LDA_S;
    constexpr int B_ELE = BK * LDB_S;
    constexpr int STG_ELE = A_ELE + B_ELE;

    extern __shared__ __align__(16) char smem_raw[];
    __half* stg = (__half*)smem_raw;

    const int tid  = threadIdx.x;
    const int bm   = blockIdx.y * BM;
    const int bn   = blockIdx.x * BN;
    const int warp = tid >> 5;
    const int wm   = (warp & 1) * 64;
    const int wn   = (warp >> 1) * (BN / 2);

    wmma::fragment<wmma::accumulator, 16, 16, 16, float> c[MI][NJ];
#pragma unroll
    for (int i = 0; i < MI; i++)
#pragma unroll
        for (int j = 0; j < NJ; j++) wmma::fill_fragment(c[i][j], 0.0f);

    const int nK = K / BK;

    auto load_stage = [&](int kt, int s) {
        __half* As = stg + s * STG_ELE;
        __half* Bs = As + A_ELE;
#pragma unroll
        for (int i = 0; i < 4; i++) {
            int idx = tid + i * NTHR;
            int r  = idx >> 2;
            int cc = (idx & 3) * 8;
            __pipeline_memcpy_async(&As[r * LDA_S + cc],
                                    &A[(size_t)(bm + r) * K + kt + cc], 16);
        }
        constexpr int CH = BN / 8;
        constexpr int NB = (BK * CH) / NTHR;
#pragma unroll
        for (int i = 0; i < NB; i++) {
            int idx = tid + i * NTHR;
            int r  = idx / CH;
            int cc = (idx % CH) * 8;
            __pipeline_memcpy_async(&Bs[r * LDB_S + cc],
                                    &B[(size_t)(kt + r) * Nc + bn + cc], 16);
        }
    };

#pragma unroll
    for (int s = 0; s < STAGES - 1; s++) {
        if (s < nK) load_stage(s * BK, s);
        __pipeline_commit();
    }

    for (int kt_i = 0; kt_i < nK; kt_i++) {
        __pipeline_wait_prior(STAGES - 2);
        __syncthreads();
        int ldk = kt_i + STAGES - 1;
        if (ldk < nK) load_stage(ldk * BK, ldk % STAGES);
        __pipeline_commit();

        int s = kt_i % STAGES;
        __half* As = stg + s * STG_ELE;
        __half* Bs = As + A_ELE;
#pragma unroll
        for (int kk = 0; kk < BK; kk += 16) {
            wmma::fragment<wmma::matrix_a, 16, 16, 16, __half, wmma::row_major> a[MI];
            wmma::fragment<wmma::matrix_b, 16, 16, 16, __half, wmma::row_major> b[NJ];
#pragma unroll
            for (int i = 0; i < MI; i++)
                wmma::load_matrix_sync(a[i], &As[(wm + i * 16) * LDA_S + kk], LDA_S);
#pragma unroll
            for (int j = 0; j < NJ; j++)
                wmma::load_matrix_sync(b[j], &Bs[kk * LDB_S + wn + j * 16], LDB_S);
#pragma unroll
            for (int i = 0; i < MI; i++)
#pragma unroll
                for (int j = 0; j < NJ; j++)
                    wmma::mma_sync(c[i][j], a[i], b[j], c[i][j]);
        }
    }

    // ---- epilogue ----
    if (EPI == EPI_SWIGLU) {
        // position-dependent (g,u) pairing: stage through smem, two 64-row passes
        __syncthreads();
        float* Cs = (float*)smem_raw;
        constexpr int F4R = BN / 4;
        constexpr int NIT = (64 * F4R) / NTHR;
#pragma unroll
        for (int hrow = 0; hrow < 2; hrow++) {
            __syncthreads();
            if ((wm >> 6) == hrow) {
#pragma unroll
                for (int i = 0; i < MI; i++)
#pragma unroll
                    for (int j = 0; j < NJ; j++)
                        wmma::store_matrix_sync(&Cs[((wm & 63) + i * 16) * LDC_S + wn + j * 16],
                                                c[i][j], LDC_S, wmma::mem_row_major);
            }
            __syncthreads();
#pragma unroll
            for (int i = 0; i < NIT; i++) {
                int e  = tid + i * NTHR;
                int r  = e / F4R;
                int cc = (e % F4R) * 4;
                float4 vv = *(float4*)&Cs[r * LDC_S + cc];
                int grow = bm + hrow * 64 + r;
                float s0 = vv.x / (1.0f + expf(-vv.x)) * vv.y;
                float s1 = vv.z / (1.0f + expf(-vv.z)) * vv.w;
                int jo = (bn + cc) >> 1;
                *(__half2*)&((__half*)Cout)[(size_t)grow * (Nc >> 1) + jo] =
                    __floats2half2_rn(s0, s1);
            }
        }
    } else {
        // fragment-direct epilogues (no smem, no syncs)
#pragma unroll
        for (int i = 0; i < MI; i++) {
#pragma unroll
            for (int j = 0; j < NJ; j++) {
                int grow = bm + wm + i * 16;
                int gcol = bn + wn + j * 16;
                if (EPI == EPI_RES) {
                    wmma::fragment<wmma::accumulator, 16, 16, 16, float> xf;
                    float* o = (float*)Cout + (size_t)grow * Nc + gcol;
                    wmma::load_matrix_sync(xf, X + (size_t)grow * Nc + gcol, Nc,
                                           wmma::mem_row_major);
#pragma unroll
                    for (int t = 0; t < xf.num_elements; t++)
                        xf.x[t] += c[i][j].x[t];
                    wmma::store_matrix_sync(o, xf, Nc, wmma::mem_row_major);
                } else {
                    wmma::fragment<wmma::accumulator, 16, 16, 16, __half> ch;
#pragma unroll
                    for (int t = 0; t < ch.num_elements; t++) {
                        float v = c[i][j].x[t];
                        if (EPI == EPI_EXPABS) v = expf(-fabsf(v));
                        ch.x[t] = __float2half(v);
                    }
                    __half* dst; int ld, c0;
                    if (EPI == EPI_QKV) {
                        if (gcol < 512)      { dst = (__half*)Cout;                    ld = 512; c0 = gcol; }
                        else if (gcol < 640) { dst = (__half*)Cout + (size_t)M * 512;  ld = 128; c0 = gcol - 512; }
                        else                 { dst = (__half*)Cout + (size_t)M * 640;  ld = 128; c0 = gcol - 640; }
                    } else {
                        dst = (__half*)Cout; ld = Nc; c0 = gcol;
                    }
                    wmma::store_matrix_sync(dst + (size_t)grow * ld + c0, ch, ld,
                                            wmma::mem_row_major);
                }
            }
        }
    }
}

// ---------------- gather + rmsnorm ----------------
__global__ __launch_bounds__(128) void gather_rmsnorm_kernel(
    const int* __restrict__ ids, const float* __restrict__ emb,
    const float* __restrict__ xin, const float* __restrict__ g,
    float* __restrict__ xout, __half* __restrict__ h)
{
    int token = blockIdx.x;
    const float* src = ids ? (emb + (size_t)ids[token] * DMODEL)
                           : (xin + (size_t)token * DMODEL);
    int c = threadIdx.x * 4;
    float4 v = *(const float4*)&src[c];
    float ss = v.x * v.x + v.y * v.y + v.z * v.z + v.w * v.w;
#pragma unroll
    for (int off = 16; off > 0; off >>= 1) ss += __shfl_xor_sync(0xffffffffu, ss, off);
    __shared__ float sred[4];
    int warp = threadIdx.x >> 5, lane = threadIdx.x & 31;
    if (lane == 0) sred[warp] = ss;
    __syncthreads();
    float tot = sred[0] + sred[1] + sred[2] + sred[3];
    float scale = rsqrtf(tot * (1.0f / DMODEL) + EPSV);
    float4 gv = *(const float4*)&g[c];
    float4 o;
    o.x = v.x * scale * gv.x; o.y = v.y * scale * gv.y;
    o.z = v.z * scale * gv.z; o.w = v.w * scale * gv.w;
    if (xout) *(float4*)&xout[(size_t)token * DMODEL + c] = v;
    *(half4*)&h[(size_t)token * DMODEL + c] = f4_to_h4(o);
}

// ---------------- kv state partials (32 chunks, 16-token tiles) ----------------
__global__ __launch_bounds__(256) void kv_partial_kernel(
    const __half* __restrict__ pk, const __half* __restrict__ v, float* __restrict__ kvp)
{
    int pair = blockIdx.x, chunk = blockIdx.y;
    int b = pair >> 1, kh = pair & 1;
    int tid = threadIdx.x;
    int ti = tid >> 4, tj = tid & 15;
    float acc[4][4], zacc[4];
#pragma unroll
    for (int a = 0; a < 4; a++) { zacc[a] = 0.f;
#pragma unroll
        for (int bb = 0; bb < 4; bb++) acc[a][bb] = 0.f; }
    __shared__ float spk[16][64], sv[16][64];
    const int CL = SEQ / KCHUNK;     // 256 tokens per chunk
    int s0 = chunk * CL;
    for (int sb = 0; sb < CL; sb += 16) {
#pragma unroll
        for (int j = 0; j < 4; j++) {
            int idx = tid + j * 256;
            int t = idx >> 6, lane = idx & 63;
            int token = b * SEQ + s0 + sb + t;
            size_t base = ((size_t)token * NKV + kh) * 64 + lane;
            spk[t][lane] = __half2float(pk[base]);
            sv[t][lane]  = __half2float(v[base]);
        }
        __syncthreads();
#pragma unroll
        for (int t = 0; t < 16; t++) {
            float pm[4], vd[4];
#pragma unroll
            for (int mm = 0; mm < 4; mm++) pm[mm] = spk[t][ti * 4 + mm];
#pragma unroll
            for (int dd = 0; dd < 4; dd++) vd[dd] = sv[t][tj * 4 + dd];
#pragma unroll
            for (int mm = 0; mm < 4; mm++) {
#pragma unroll
                for (int dd = 0; dd < 4; dd++) acc[mm][dd] = fmaf(pm[mm], vd[dd], acc[mm][dd]);
                if (tj == 0) zacc[mm] += pm[mm];
            }
        }
        __syncthreads();
    }
    int pc = pair * KCHUNK + chunk;
#pragma unroll
    for (int mm = 0; mm < 4; mm++) {
#pragma unroll
        for (int dd = 0; dd < 4; dd++)
            kvp[(size_t)pc * 4160 + (ti * 4 + mm) * 65 + tj * 4 + dd] = acc[mm][dd];
        if (tj == 0) kvp[(size_t)pc * 4160 + (ti * 4 + mm) * 65 + 64] = zacc[mm];
    }
}

// ---------------- kv reduce: grid (16, 8); each block reduces 520 elems ----------------
__global__ __launch_bounds__(256) void kv_reduce_kernel(
    const float* __restrict__ kvp, float* __restrict__ kv)
{
    int pair = blockIdx.x;
    int seg  = blockIdx.y;
    int lo = seg * 520, hi = lo + 520;
    for (int idx = lo + threadIdx.x; idx < hi; idx += 256) {
        float s = 0.f;
#pragma unroll
        for (int c = 0; c < KCHUNK; c++)
            s += kvp[(size_t)(pair * KCHUNK + c) * 4160 + idx];
        kv[(size_t)pair * 4160 + idx] = s;
    }
}

// ---------------- num/den ----------------
__global__ __launch_bounds__(256) void numden_kernel(
    const __half* __restrict__ pq, const float* __restrict__ kvg, __half* __restrict__ att)
{
    int b = blockIdx.y;
    __shared__ float skv[2 * 64 * 65];
    __shared__ float spq[4][64];
    for (int idx = threadIdx.x; idx < 8320; idx += 256)
        skv[idx] = kvg[(size_t)b * 8320 + idx];
    __syncthreads();
    int group = threadIdx.x >> 6, lane = threadIdx.x & 63;
    int base = blockIdx.x * 128;
    for (int it = 0; it < 32; it++) {
        int th = base + it * 4 + group;
        size_t row = ((size_t)b * (SEQ * NHEAD) + th) * 64;
        spq[group][lane] = __half2float(pq[row + lane]);
        __syncthreads();
        int h = th & 7;
        const float* kvh = &skv[(h >> 2) * 4160];
        float num = 0.f, den = 0.f;
#pragma unroll
        for (int m = 0; m < 64; m++) {
            float p = spq[group][m];
            num = fmaf(p, kvh[m * 65 + lane], num);
            den = fmaf(p, kvh[m * 65 + 64], den);
        }
        att[row + lane] = __float2half(num / (den + EPSV));
        __syncthreads();
    }
}

// ---------------- pool + head ----------------
__global__ __launch_bounds__(256) void pool_kernel(
    const float* __restrict__ x, float* __restrict__ xm)
{
    int b = blockIdx.y;
    int c = blockIdx.x * 64 + (threadIdx.x & 63);
    int part = threadIdx.x >> 6;
    float s = 0.f;
    for (int t = part; t < SEQ; t += 4)
        s += x[((size_t)b * SEQ + t) * DMODEL + c];
    __shared__ float red[4][64];
    red[part][threadIdx.x & 63] = s;
    __syncthreads();
    if (part == 0) {
        int l = threadIdx.x & 63;
        xm[b * DMODEL + c] = red[0][l] + red[1][l] + red[2][l] + red[3][l];
    }
}

__global__ __launch_bounds__(512) void head_kernel(
    const float* __restrict__ xm, const float* __restrict__ Wc,
    const float* __restrict__ bc, float* __restrict__ out)
{
    int warp = threadIdx.x >> 5, lane = threadIdx.x & 31;
    int b = warp >> 1, cls = warp & 1;
    float s = 0.f;
    for (int d = lane; d < DMODEL; d += 32)
        s += xm[b * DMODEL + d] * Wc[d * NCLS + cls];
#pragma unroll
    for (int off = 16; off > 0; off >>= 1) s += __shfl_xor_sync(0xffffffffu, s, off);
    if (lane == 0) out[b * NCLS + cls] = s * (1.0f / SEQ) + bc[cls];
}

// ---------------- launch ----------------
#define SMEM_BN128_V (STAGES * (128 * 40 + 32 * 136) * 2)   // 75776
#define SMEM_BN64_V  (STAGES * (128 * 40 + 32 * 72) * 2)    // 59392

extern "C" void kernel_launch(void* const* d_in, const int* in_sizes, int n_in,
                              void* d_out, int out_size)
{
    (void)in_sizes; (void)n_in; (void)out_size;
    const int*   ids  = (const int*)  d_in[0];
    const float* emb  = (const float*)d_in[1];
    const float* Wq   = (const float*)d_in[2];
    const float* Wk   = (const float*)d_in[3];
    const float* Wv   = (const float*)d_in[4];
    const float* Wphi = (const float*)d_in[5];
    const float* Wo   = (const float*)d_in[6];
    const float* g1   = (const float*)d_in[7];
    const float* g2   = (const float*)d_in[8];
    const float* Wg   = (const float*)d_in[9];
    const float* Wu   = (const float*)d_in[10];
    const float* Wd   = (const float*)d_in[11];
    const float* Wc   = (const float*)d_in[12];
    const float* bc   = (const float*)d_in[13];
    float* out = (float*)d_out;

    float *x, *kvp, *kv, *xm;
    __half *h, *qkv, *pqk, *att, *gu;
    __half *WqkvH, *WphiH, *WoH, *WguH, *WdH;
    cudaGetSymbolAddress((void**)&x,    g_x);
    cudaGetSymbolAddress((void**)&h,    g_h);
    cudaGetSymbolAddress((void**)&qkv,  g_qkv);
    cudaGetSymbolAddress((void**)&pqk,  g_pqk);
    cudaGetSymbolAddress((void**)&att,  g_att);
    cudaGetSymbolAddress((void**)&gu,   g_gu);
    cudaGetSymbolAddress((void**)&kvp,  g_kvp);
    cudaGetSymbolAddress((void**)&kv,   g_kv);
    cudaGetSymbolAddress((void**)&xm,   g_xm);
    cudaGetSymbolAddress((void**)&WqkvH, g_WqkvH);
    cudaGetSymbolAddress((void**)&WphiH, g_WphiH);
    cudaGetSymbolAddress((void**)&WoH,   g_WoH);
    cudaGetSymbolAddress((void**)&WguH,  g_WguH);
    cudaGetSymbolAddress((void**)&WdH,   g_WdH);

    cudaFuncSetAttribute(gemm_h<128, EPI_QKV>,    cudaFuncAttributeMaxDynamicSharedMemorySize, SMEM_BN128_V);
    cudaFuncSetAttribute(gemm_h<128, EPI_RES>,    cudaFuncAttributeMaxDynamicSharedMemorySize, SMEM_BN128_V);
    cudaFuncSetAttribute(gemm_h<128, EPI_SWIGLU>, cudaFuncAttributeMaxDynamicSharedMemorySize, SMEM_BN128_V);
    cudaFuncSetAttribute(gemm_h<64,  EPI_EXPABS>, cudaFuncAttributeMaxDynamicSharedMemorySize, SMEM_BN64_V);

    // 1. merged weight conversion
    conv_all<<<(CTOT + 255) / 256, 256>>>(Wq, Wk, Wv, Wg, Wu, Wphi, Wo, Wd,
                                          WqkvH, WguH, WphiH, WoH, WdH);

    // 2. embedding gather + rmsnorm
    gather_rmsnorm_kernel<<<NTOK, 128>>>(ids, emb, nullptr, g1, x, h);

    // 3. fused qkv projection
    {
        dim3 grid(768 / 128, NTOK / 128);
        gemm_h<128, EPI_QKV><<<grid, NTHR, SMEM_BN128_V>>>(h, WqkvH, qkv, nullptr, NTOK, DMODEL, 768);
    }

    // 4. single Laplacian feature-map GEMM over q-rows + k-rows
    {
        dim3 grid(1, NTOK * (NHEAD + NKV) / 128);
        gemm_h<64, EPI_EXPABS><<<grid, NTHR, SMEM_BN64_V>>>(
            qkv, WphiH, pqk, nullptr, NTOK * (NHEAD + NKV), DHEAD, MFEAT);
    }

    // 5. global kv state partials (chip-filling) + cheap separate reduce
    {
        dim3 gp(BATCH * NKV, KCHUNK);
        kv_partial_kernel<<<gp, 256>>>(pqk + (size_t)NTOK * NHEAD * MFEAT,
                                       qkv + (size_t)NTOK * 640, kvp);
        dim3 gr(BATCH * NKV, 8);
        kv_reduce_kernel<<<gr, 256>>>(kvp, kv);
    }

    // 6. num/den -> attn (broadcast load of reduced kv)
    {
        dim3 gn(SEQ * NHEAD / 128, BATCH);
        numden_kernel<<<gn, 256>>>(pqk, kv, att);
    }

    // 7. output projection + residual
    {
        dim3 grid(DMODEL / 128, NTOK / 128);
        gemm_h<128, EPI_RES><<<grid, NTHR, SMEM_BN128_V>>>(att, WoH, x, x, NTOK, DMODEL, DMODEL);
    }

    // 8. pre-FFN rmsnorm
    gather_rmsnorm_kernel<<<NTOK, 128>>>(nullptr, nullptr, x, g2, nullptr, h);

    // 9. fused SwiGLU up
    {
        dim3 grid(4096 / 128, NTOK / 128);
        gemm_h<128, EPI_SWIGLU><<<grid, NTHR, SMEM_BN128_V>>>(h, WguH, gu, nullptr, NTOK, DMODEL, 4096);
    }
    // 10. down proj + residual
    {
        dim3 grid(DMODEL / 128, NTOK / 128);
        gemm_h<128, EPI_RES><<<grid, NTHR, SMEM_BN128_V>>>(gu, WdH, x, x, NTOK, DFF, DMODEL);
    }

    // 11. mean pool + head
    {
        dim3 gpool(DMODEL / 64, BATCH);
        pool_kernel<<<gpool, 256>>>(x, xm);
    }
    head_kernel<<<1, 512>>>(xm, Wc, bc, out);
}

// round 14
// speedup vs baseline: 1.3818x; 1.2066x over previous
#include <cuda_runtime.h>
#include <cuda_fp16.h>
#include <cuda_pipeline.h>
#include <mma.h>
#include <math.h>
#include <cstdint>

using namespace nvcuda;

// ---------------- problem constants ----------------
#define NTOK   65536
#define BATCH  8
#define SEQ    8192
#define DMODEL 512
#define NHEAD  8
#define NKV    2
#define DHEAD  64
#define MFEAT  64
#define DFF    2048
#define NCLS   2
#define EPSV   1e-6f
#define KCHUNK 32

// ---------------- scratch ----------------
__device__ float  g_x   [NTOK * DMODEL];
__device__ __half g_h   [NTOK * DMODEL];
__device__ __half g_qkv [NTOK * (DMODEL + 2*128)];   // q | k | v contiguous blocks
__device__ __half g_pqk [NTOK * (NHEAD + NKV) * MFEAT];  // pq rows then pk rows
__device__ __half g_att [NTOK * DMODEL];
__device__ __half g_gu  [NTOK * DFF];
__device__ float  g_kvp [16 * KCHUNK * 64 * 65];
__device__ __half g_kvh [16 * 64 * 64];   // reduced kv state, fp16 (d cols)
__device__ float  g_z   [16 * 64];        // reduced normalizer, fp32
__device__ float  g_xm  [BATCH * DMODEL];
// converted fp16 weights, row-major [K, N]
__device__ __half g_WqkvH[DMODEL * 768];
__device__ __half g_WphiH[DHEAD * MFEAT];
__device__ __half g_WoH  [DMODEL * DMODEL];
__device__ __half g_WguH [DMODEL * (2*DFF)];   // interleaved g,u columns
__device__ __half g_WdH  [DFF * DMODEL];

struct alignas(8) half4 { __half2 a, b; };
__device__ __forceinline__ half4 f4_to_h4(float4 v) {
    half4 r; r.a = __floats2half2_rn(v.x, v.y); r.b = __floats2half2_rn(v.z, v.w); return r;
}

// ---------------- single merged weight conversion ----------------
#define CQKV 393216
#define CGU  2097152
#define CPHI 4096
#define CWO  262144
#define CWD  1048576
#define CTOT (CQKV + CGU + CPHI + CWO + CWD)

__global__ void conv_all(const float* __restrict__ Wq, const float* __restrict__ Wk,
                         const float* __restrict__ Wv, const float* __restrict__ Wg,
                         const float* __restrict__ Wu, const float* __restrict__ Wphi,
                         const float* __restrict__ Wo, const float* __restrict__ Wd,
                         __half* __restrict__ WqkvH, __half* __restrict__ WguH,
                         __half* __restrict__ WphiH, __half* __restrict__ WoH,
                         __half* __restrict__ WdH)
{
    int idx = blockIdx.x * 256 + threadIdx.x;
    if (idx < CQKV) {
        int r = idx / 768, c = idx % 768;
        float v = (c < 512) ? Wq[r * 512 + c]
                            : (c < 640 ? Wk[r * 128 + c - 512] : Wv[r * 128 + c - 640]);
        WqkvH[idx] = __float2half(v);
        return;
    }
    idx -= CQKV;
    if (idx < CGU) {
        int r = idx >> 12, c = idx & 4095;
        int j = c >> 1;
        float v = (c & 1) ? Wu[r * DFF + j] : Wg[r * DFF + j];
        WguH[idx] = __float2half(v);
        return;
    }
    idx -= CGU;
    if (idx < CPHI) { WphiH[idx] = __float2half(Wphi[idx]); return; }
    idx -= CPHI;
    if (idx < CWO)  { WoH[idx]   = __float2half(Wo[idx]);   return; }
    idx -= CWO;
    if (idx < CWD)  { WdH[idx]   = __float2half(Wd[idx]);   return; }
}

// ---------------- fp16 WMMA GEMM: 128 thr, 64x64 warp tile, 4 stages ----------------
#define EPI_QKV    0
#define EPI_EXPABS 1
#define EPI_RES    2
#define EPI_SWIGLU 3
#define STAGES 4
#define NTHR   128

template<int BN, int EPI>
__global__ __launch_bounds__(NTHR, 3) void gemm_h(
    const __half* __restrict__ A, const __half* __restrict__ B,
    void* __restrict__ Cout, const float* __restrict__ X,
    int M, int K, int Nc)
{
    constexpr int BM = 128, BK = 32;
    constexpr int LDA_S = BK + 8;
    constexpr int LDB_S = BN + 8;
    constexpr int LDC_S = BN + 4;
    constexpr int MI = 4;               // 64/16 m-frags per warp
    constexpr int NJ = BN / 32;         // warp n-tile = BN/2
    constexpr int A_ELE = BM * LDA_S;
    constexpr int B_ELE = BK * LDB_S;
    constexpr int STG_ELE = A_ELE + B_ELE;

    extern __shared__ __align__(16) char smem_raw[];
    __half* stg = (__half*)smem_raw;

    const int tid  = threadIdx.x;
    const int bm   = blockIdx.y * BM;
    const int bn   = blockIdx.x * BN;
    const int warp = tid >> 5;
    const int wm   = (warp & 1) * 64;
    const int wn   = (warp >> 1) * (BN / 2);

    wmma::fragment<wmma::accumulator, 16, 16, 16, float> c[MI][NJ];
#pragma unroll
    for (int i = 0; i < MI; i++)
#pragma unroll
        for (int j = 0; j < NJ; j++) wmma::fill_fragment(c[i][j], 0.0f);

    const int nK = K / BK;

    auto load_stage = [&](int kt, int s) {
        __half* As = stg + s * STG_ELE;
        __half* Bs = As + A_ELE;
#pragma unroll
        for (int i = 0; i < 4; i++) {
            int idx = tid + i * NTHR;
            int r  = idx >> 2;
            int cc = (idx & 3) * 8;
            __pipeline_memcpy_async(&As[r * LDA_S + cc],
                                    &A[(size_t)(bm + r) * K + kt + cc], 16);
        }
        constexpr int CH = BN / 8;
        constexpr int NB = (BK * CH) / NTHR;
#pragma unroll
        for (int i = 0; i < NB; i++) {
            int idx = tid + i * NTHR;
            int r  = idx / CH;
            int cc = (idx % CH) * 8;
            __pipeline_memcpy_async(&Bs[r * LDB_S + cc],
                                    &B[(size_t)(kt + r) * Nc + bn + cc], 16);
        }
    };

#pragma unroll
    for (int s = 0; s < STAGES - 1; s++) {
        if (s < nK) load_stage(s * BK, s);
        __pipeline_commit();
    }

    for (int kt_i = 0; kt_i < nK; kt_i++) {
        __pipeline_wait_prior(STAGES - 2);
        __syncthreads();
        int ldk = kt_i + STAGES - 1;
        if (ldk < nK) load_stage(ldk * BK, ldk % STAGES);
        __pipeline_commit();

        int s = kt_i % STAGES;
        __half* As = stg + s * STG_ELE;
        __half* Bs = As + A_ELE;
#pragma unroll
        for (int kk = 0; kk < BK; kk += 16) {
            wmma::fragment<wmma::matrix_a, 16, 16, 16, __half, wmma::row_major> a[MI];
            wmma::fragment<wmma::matrix_b, 16, 16, 16, __half, wmma::row_major> b[NJ];
#pragma unroll
            for (int i = 0; i < MI; i++)
                wmma::load_matrix_sync(a[i], &As[(wm + i * 16) * LDA_S + kk], LDA_S);
#pragma unroll
            for (int j = 0; j < NJ; j++)
                wmma::load_matrix_sync(b[j], &Bs[kk * LDB_S + wn + j * 16], LDB_S);
#pragma unroll
            for (int i = 0; i < MI; i++)
#pragma unroll
                for (int j = 0; j < NJ; j++)
                    wmma::mma_sync(c[i][j], a[i], b[j], c[i][j]);
        }
    }

    // ---- epilogue ----
    if (EPI == EPI_SWIGLU) {
        // position-dependent (g,u) pairing: stage through smem, two 64-row passes
        __syncthreads();
        float* Cs = (float*)smem_raw;
        constexpr int F4R = BN / 4;
        constexpr int NIT = (64 * F4R) / NTHR;
#pragma unroll
        for (int hrow = 0; hrow < 2; hrow++) {
            __syncthreads();
            if ((wm >> 6) == hrow) {
#pragma unroll
                for (int i = 0; i < MI; i++)
#pragma unroll
                    for (int j = 0; j < NJ; j++)
                        wmma::store_matrix_sync(&Cs[((wm & 63) + i * 16) * LDC_S + wn + j * 16],
                                                c[i][j], LDC_S, wmma::mem_row_major);
            }
            __syncthreads();
#pragma unroll
            for (int i = 0; i < NIT; i++) {
                int e  = tid + i * NTHR;
                int r  = e / F4R;
                int cc = (e % F4R) * 4;
                float4 vv = *(float4*)&Cs[r * LDC_S + cc];
                int grow = bm + hrow * 64 + r;
                float s0 = vv.x / (1.0f + expf(-vv.x)) * vv.y;
                float s1 = vv.z / (1.0f + expf(-vv.z)) * vv.w;
                int jo = (bn + cc) >> 1;
                *(__half2*)&((__half*)Cout)[(size_t)grow * (Nc >> 1) + jo] =
                    __floats2half2_rn(s0, s1);
            }
        }
    } else {
        // fragment-direct epilogues (no smem, no syncs)
#pragma unroll
        for (int i = 0; i < MI; i++) {
#pragma unroll
            for (int j = 0; j < NJ; j++) {
                int grow = bm + wm + i * 16;
                int gcol = bn + wn + j * 16;
                if (EPI == EPI_RES) {
                    wmma::fragment<wmma::accumulator, 16, 16, 16, float> xf;
                    float* o = (float*)Cout + (size_t)grow * Nc + gcol;
                    wmma::load_matrix_sync(xf, X + (size_t)grow * Nc + gcol, Nc,
                                           wmma::mem_row_major);
#pragma unroll
                    for (int t = 0; t < xf.num_elements; t++)
                        xf.x[t] += c[i][j].x[t];
                    wmma::store_matrix_sync(o, xf, Nc, wmma::mem_row_major);
                } else {
                    wmma::fragment<wmma::accumulator, 16, 16, 16, __half> ch;
#pragma unroll
                    for (int t = 0; t < ch.num_elements; t++) {
                        float v = c[i][j].x[t];
                        if (EPI == EPI_EXPABS) v = expf(-fabsf(v));
                        ch.x[t] = __float2half(v);
                    }
                    __half* dst; int ld, c0;
                    if (EPI == EPI_QKV) {
                        if (gcol < 512)      { dst = (__half*)Cout;                    ld = 512; c0 = gcol; }
                        else if (gcol < 640) { dst = (__half*)Cout + (size_t)M * 512;  ld = 128; c0 = gcol - 512; }
                        else                 { dst = (__half*)Cout + (size_t)M * 640;  ld = 128; c0 = gcol - 640; }
                    } else {
                        dst = (__half*)Cout; ld = Nc; c0 = gcol;
                    }
                    wmma::store_matrix_sync(dst + (size_t)grow * ld + c0, ch, ld,
                                            wmma::mem_row_major);
                }
            }
        }
    }
}

// ---------------- gather + rmsnorm ----------------
__global__ __launch_bounds__(128) void gather_rmsnorm_kernel(
    const int* __restrict__ ids, const float* __restrict__ emb,
    const float* __restrict__ xin, const float* __restrict__ g,
    float* __restrict__ xout, __half* __restrict__ h)
{
    int token = blockIdx.x;
    const float* src = ids ? (emb + (size_t)ids[token] * DMODEL)
                           : (xin + (size_t)token * DMODEL);
    int c = threadIdx.x * 4;
    float4 v = *(const float4*)&src[c];
    float ss = v.x * v.x + v.y * v.y + v.z * v.z + v.w * v.w;
#pragma unroll
    for (int off = 16; off > 0; off >>= 1) ss += __shfl_xor_sync(0xffffffffu, ss, off);
    __shared__ float sred[4];
    int warp = threadIdx.x >> 5, lane = threadIdx.x & 31;
    if (lane == 0) sred[warp] = ss;
    __syncthreads();
    float tot = sred[0] + sred[1] + sred[2] + sred[3];
    float scale = rsqrtf(tot * (1.0f / DMODEL) + EPSV);
    float4 gv = *(const float4*)&g[c];
    float4 o;
    o.x = v.x * scale * gv.x; o.y = v.y * scale * gv.y;
    o.z = v.z * scale * gv.z; o.w = v.w * scale * gv.w;
    if (xout) *(float4*)&xout[(size_t)token * DMODEL + c] = v;
    *(half4*)&h[(size_t)token * DMODEL + c] = f4_to_h4(o);
}

// ---------------- kv state partials (32 chunks, 16-token tiles) ----------------
__global__ __launch_bounds__(256) void kv_partial_kernel(
    const __half* __restrict__ pk, const __half* __restrict__ v, float* __restrict__ kvp)
{
    int pair = blockIdx.x, chunk = blockIdx.y;
    int b = pair >> 1, kh = pair & 1;
    int tid = threadIdx.x;
    int ti = tid >> 4, tj = tid & 15;
    float acc[4][4], zacc[4];
#pragma unroll
    for (int a = 0; a < 4; a++) { zacc[a] = 0.f;
#pragma unroll
        for (int bb = 0; bb < 4; bb++) acc[a][bb] = 0.f; }
    __shared__ float spk[16][64], sv[16][64];
    const int CL = SEQ / KCHUNK;     // 256 tokens per chunk
    int s0 = chunk * CL;
    for (int sb = 0; sb < CL; sb += 16) {
#pragma unroll
        for (int j = 0; j < 4; j++) {
            int idx = tid + j * 256;
            int t = idx >> 6, lane = idx & 63;
            int token = b * SEQ + s0 + sb + t;
            size_t base = ((size_t)token * NKV + kh) * 64 + lane;
            spk[t][lane] = __half2float(pk[base]);
            sv[t][lane]  = __half2float(v[base]);
        }
        __syncthreads();
#pragma unroll
        for (int t = 0; t < 16; t++) {
            float pm[4], vd[4];
#pragma unroll
            for (int mm = 0; mm < 4; mm++) pm[mm] = spk[t][ti * 4 + mm];
#pragma unroll
            for (int dd = 0; dd < 4; dd++) vd[dd] = sv[t][tj * 4 + dd];
#pragma unroll
            for (int mm = 0; mm < 4; mm++) {
#pragma unroll
                for (int dd = 0; dd < 4; dd++) acc[mm][dd] = fmaf(pm[mm], vd[dd], acc[mm][dd]);
                if (tj == 0) zacc[mm] += pm[mm];
            }
        }
        __syncthreads();
    }
    int pc = pair * KCHUNK + chunk;
#pragma unroll
    for (int mm = 0; mm < 4; mm++) {
#pragma unroll
        for (int dd = 0; dd < 4; dd++)
            kvp[(size_t)pc * 4160 + (ti * 4 + mm) * 65 + tj * 4 + dd] = acc[mm][dd];
        if (tj == 0) kvp[(size_t)pc * 4160 + (ti * 4 + mm) * 65 + 64] = zacc[mm];
    }
}

// ---------------- kv reduce -> fp16 kv_d + fp32 z ----------------
__global__ __launch_bounds__(256) void kv_reduce_kernel(
    const float* __restrict__ kvp, __half* __restrict__ kvh, float* __restrict__ z)
{
    int pair = blockIdx.x;
    int seg  = blockIdx.y;                 // grid (16, 8), 520 elems per seg
    int lo = seg * 520, hi = lo + 520;
    for (int idx = lo + threadIdx.x; idx < hi; idx += 256) {
        float s = 0.f;
#pragma unroll
        for (int c = 0; c < KCHUNK; c++)
            s += kvp[(size_t)(pair * KCHUNK + c) * 4160 + idx];
        int m = idx / 65, col = idx % 65;
        if (col < 64) kvh[(size_t)pair * 4096 + m * 64 + col] = __float2half(s);
        else          z[pair * 64 + m] = s;
    }
}

// ---------------- tensor-core num + fp32 den -> attn ----------------
// grid (NTOK/128, NHEAD), 128 threads. num = pq_head @ kv_d (fp16 MMA, fp32 acc);
// den = pq_head . z in exact fp32; att = num/(den+eps).
__global__ __launch_bounds__(128) void numden_tc_kernel(
    const __half* __restrict__ pq, const __half* __restrict__ kvh,
    const float* __restrict__ zg, __half* __restrict__ att)
{
    __shared__ __half kvs[64 * 72];
    __shared__ float  zs[64];
    __shared__ float  Cs[128 * 68];

    const int tid  = threadIdx.x;
    const int h    = blockIdx.y;
    const int kh   = h >> 2;
    const int tok0 = blockIdx.x * 128;
    const int pair = (tok0 >> 13) * 2 + kh;    // batch*2 + kh (128 | 8192)

    // stage kv_d [64x64] -> smem [64x72]
#pragma unroll
    for (int i = 0; i < 4; i++) {
        int e = tid + i * 128;                 // 512 chunks of 8 halves
        int r = e >> 3, c8 = (e & 7) * 8;
        *(uint4*)&kvs[r * 72 + c8] = *(const uint4*)&kvh[(size_t)pair * 4096 + r * 64 + c8];
    }
    if (tid < 64) zs[tid] = zg[pair * 64 + tid];
    __syncthreads();

    const int warp = tid >> 5;
    wmma::fragment<wmma::accumulator, 16, 16, 16, float> c[2][4];
#pragma unroll
    for (int i = 0; i < 2; i++)
#pragma unroll
        for (int j = 0; j < 4; j++) wmma::fill_fragment(c[i][j], 0.0f);

    const __half* Abase = pq + (size_t)(tok0 + warp * 32) * 512 + h * 64;
#pragma unroll
    for (int kk = 0; kk < 64; kk += 16) {
        wmma::fragment<wmma::matrix_a, 16, 16, 16, __half, wmma::row_major> a[2];
        wmma::fragment<wmma::matrix_b, 16, 16, 16, __half, wmma::row_major> b[4];
#pragma unroll
        for (int i = 0; i < 2; i++)
            wmma::load_matrix_sync(a[i], Abase + (size_t)i * 16 * 512 + kk, 512);
#pragma unroll
        for (int j = 0; j < 4; j++)
            wmma::load_matrix_sync(b[j], &kvs[kk * 72 + j * 16], 72);
#pragma unroll
        for (int i = 0; i < 2; i++)
#pragma unroll
            for (int j = 0; j < 4; j++)
                wmma::mma_sync(c[i][j], a[i], b[j], c[i][j]);
    }
#pragma unroll
    for (int i = 0; i < 2; i++)
#pragma unroll
        for (int j = 0; j < 4; j++)
            wmma::store_matrix_sync(&Cs[(warp * 32 + i * 16) * 68 + j * 16],
                                    c[i][j], 68, wmma::mem_row_major);

    // exact fp32 den for this thread's token
    const __half* prow = pq + (size_t)(tok0 + tid) * 512 + h * 64;
    float den = 0.f;
#pragma unroll
    for (int m = 0; m < 64; m += 2) {
        float2 pf = __half22float2(*(const __half2*)(prow + m));
        den = fmaf(pf.x, zs[m], den);
        den = fmaf(pf.y, zs[m + 1], den);
    }
    __syncwarp();                              // own warp wrote rows [warp*32, +32)
    float rr = 1.0f / (den + EPSV);
    __half* orow = att + (size_t)(tok0 + tid) * 512 + h * 64;
#pragma unroll
    for (int d = 0; d < 64; d += 4) {
        float4 v = *(float4*)&Cs[tid * 68 + d];
        half4 hv;
        hv.a = __floats2half2_rn(v.x * rr, v.y * rr);
        hv.b = __floats2half2_rn(v.z * rr, v.w * rr);
        *(half4*)(orow + d) = hv;
    }
}

// ---------------- pool + head ----------------
__global__ __launch_bounds__(256) void pool_kernel(
    const float* __restrict__ x, float* __restrict__ xm)
{
    int b = blockIdx.y;
    int c = blockIdx.x * 64 + (threadIdx.x & 63);
    int part = threadIdx.x >> 6;
    float s = 0.f;
    for (int t = part; t < SEQ; t += 4)
        s += x[((size_t)b * SEQ + t) * DMODEL + c];
    __shared__ float red[4][64];
    red[part][threadIdx.x & 63] = s;
    __syncthreads();
    if (part == 0) {
        int l = threadIdx.x & 63;
        xm[b * DMODEL + c] = red[0][l] + red[1][l] + red[2][l] + red[3][l];
    }
}

__global__ __launch_bounds__(512) void head_kernel(
    const float* __restrict__ xm, const float* __restrict__ Wc,
    const float* __restrict__ bc, float* __restrict__ out)
{
    int warp = threadIdx.x >> 5, lane = threadIdx.x & 31;
    int b = warp >> 1, cls = warp & 1;
    float s = 0.f;
    for (int d = lane; d < DMODEL; d += 32)
        s += xm[b * DMODEL + d] * Wc[d * NCLS + cls];
#pragma unroll
    for (int off = 16; off > 0; off >>= 1) s += __shfl_xor_sync(0xffffffffu, s, off);
    if (lane == 0) out[b * NCLS + cls] = s * (1.0f / SEQ) + bc[cls];
}

// ---------------- launch ----------------
#define SMEM_BN128_V (STAGES * (128 * 40 + 32 * 136) * 2)   // 75776
#define SMEM_BN64_V  (STAGES * (128 * 40 + 32 * 72) * 2)    // 59392

extern "C" void kernel_launch(void* const* d_in, const int* in_sizes, int n_in,
                              void* d_out, int out_size)
{
    (void)in_sizes; (void)n_in; (void)out_size;
    const int*   ids  = (const int*)  d_in[0];
    const float* emb  = (const float*)d_in[1];
    const float* Wq   = (const float*)d_in[2];
    const float* Wk   = (const float*)d_in[3];
    const float* Wv   = (const float*)d_in[4];
    const float* Wphi = (const float*)d_in[5];
    const float* Wo   = (const float*)d_in[6];
    const float* g1   = (const float*)d_in[7];
    const float* g2   = (const float*)d_in[8];
    const float* Wg   = (const float*)d_in[9];
    const float* Wu   = (const float*)d_in[10];
    const float* Wd   = (const float*)d_in[11];
    const float* Wc   = (const float*)d_in[12];
    const float* bc   = (const float*)d_in[13];
    float* out = (float*)d_out;

    float *x, *kvp, *z, *xm;
    __half *h, *qkv, *pqk, *att, *gu, *kvh;
    __half *WqkvH, *WphiH, *WoH, *WguH, *WdH;
    cudaGetSymbolAddress((void**)&x,    g_x);
    cudaGetSymbolAddress((void**)&h,    g_h);
    cudaGetSymbolAddress((void**)&qkv,  g_qkv);
    cudaGetSymbolAddress((void**)&pqk,  g_pqk);
    cudaGetSymbolAddress((void**)&att,  g_att);
    cudaGetSymbolAddress((void**)&gu,   g_gu);
    cudaGetSymbolAddress((void**)&kvp,  g_kvp);
    cudaGetSymbolAddress((void**)&kvh,  g_kvh);
    cudaGetSymbolAddress((void**)&z,    g_z);
    cudaGetSymbolAddress((void**)&xm,   g_xm);
    cudaGetSymbolAddress((void**)&WqkvH, g_WqkvH);
    cudaGetSymbolAddress((void**)&WphiH, g_WphiH);
    cudaGetSymbolAddress((void**)&WoH,   g_WoH);
    cudaGetSymbolAddress((void**)&WguH,  g_WguH);
    cudaGetSymbolAddress((void**)&WdH,   g_WdH);

    cudaFuncSetAttribute(gemm_h<128, EPI_QKV>,    cudaFuncAttributeMaxDynamicSharedMemorySize, SMEM_BN128_V);
    cudaFuncSetAttribute(gemm_h<128, EPI_RES>,    cudaFuncAttributeMaxDynamicSharedMemorySize, SMEM_BN128_V);
    cudaFuncSetAttribute(gemm_h<128, EPI_SWIGLU>, cudaFuncAttributeMaxDynamicSharedMemorySize, SMEM_BN128_V);
    cudaFuncSetAttribute(gemm_h<64,  EPI_EXPABS>, cudaFuncAttributeMaxDynamicSharedMemorySize, SMEM_BN64_V);

    // 1. merged weight conversion
    conv_all<<<(CTOT + 255) / 256, 256>>>(Wq, Wk, Wv, Wg, Wu, Wphi, Wo, Wd,
                                          WqkvH, WguH, WphiH, WoH, WdH);

    // 2. embedding gather + rmsnorm
    gather_rmsnorm_kernel<<<NTOK, 128>>>(ids, emb, nullptr, g1, x, h);

    // 3. fused qkv projection
    {
        dim3 grid(768 / 128, NTOK / 128);
        gemm_h<128, EPI_QKV><<<grid, NTHR, SMEM_BN128_V>>>(h, WqkvH, qkv, nullptr, NTOK, DMODEL, 768);
    }

    // 4. single Laplacian feature-map GEMM over q-rows + k-rows
    {
        dim3 grid(1, NTOK * (NHEAD + NKV) / 128);
        gemm_h<64, EPI_EXPABS><<<grid, NTHR, SMEM_BN64_V>>>(
            qkv, WphiH, pqk, nullptr, NTOK * (NHEAD + NKV), DHEAD, MFEAT);
    }

    // 5. global kv state partials (chip-filling) + reduce -> fp16 kv_d / fp32 z
    {
        dim3 gp(BATCH * NKV, KCHUNK);
        kv_partial_kernel<<<gp, 256>>>(pqk + (size_t)NTOK * NHEAD * MFEAT,
                                       qkv + (size_t)NTOK * 640, kvp);
        dim3 gr(BATCH * NKV, 8);
        kv_reduce_kernel<<<gr, 256>>>(kvp, kvh, z);
    }

    // 6. tensor-core num + fp32 den -> attn
    {
        dim3 gn(NTOK / 128, NHEAD);
        numden_tc_kernel<<<gn, 128>>>(pqk, kvh, z, att);
    }

    // 7. output projection + residual
    {
        dim3 grid(DMODEL / 128, NTOK / 128);
        gemm_h<128, EPI_RES><<<grid, NTHR, SMEM_BN128_V>>>(att, WoH, x, x, NTOK, DMODEL, DMODEL);
    }

    // 8. pre-FFN rmsnorm
    gather_rmsnorm_kernel<<<NTOK, 128>>>(nullptr, nullptr, x, g2, nullptr, h);

    // 9. fused SwiGLU up
    {
        dim3 grid(4096 / 128, NTOK / 128);
        gemm_h<128, EPI_SWIGLU><<<grid, NTHR, SMEM_BN128_V>>>(h, WguH, gu, nullptr, NTOK, DMODEL, 4096);
    }
    // 10. down proj + residual
    {
        dim3 grid(DMODEL / 128, NTOK / 128);
        gemm_h<128, EPI_RES><<<grid, NTHR, SMEM_BN128_V>>>(gu, WdH, x, x, NTOK, DFF, DMODEL);
    }

    // 11. mean pool + head
    {
        dim3 gpool(DMODEL / 64, BATCH);
        pool_kernel<<<gpool, 256>>>(x, xm);
    }
    head_kernel<<<1, 512>>>(xm, Wc, bc, out);
}

// round 15
// speedup vs baseline: 1.4088x; 1.0195x over previous
#include <cuda_runtime.h>
#include <cuda_fp16.h>
#include <cuda_pipeline.h>
#include <mma.h>
#include <math.h>
#include <cstdint>

using namespace nvcuda;

// ---------------- problem constants ----------------
#define NTOK   65536
#define BATCH  8
#define SEQ    8192
#define DMODEL 512
#define NHEAD  8
#define NKV    2
#define DHEAD  64
#define MFEAT  64
#define DFF    2048
#define NCLS   2
#define EPSV   1e-6f
#define KCH2   16          // kv chunks of 512 tokens

// ---------------- scratch ----------------
__device__ __half g_x   [NTOK * DMODEL];          // fp16 residual stream
__device__ __half g_h   [NTOK * DMODEL];
__device__ __half g_qkv [NTOK * (DMODEL + 2*128)];   // q | k | v contiguous
__device__ __half g_pqk [NTOK * (NHEAD + NKV) * MFEAT];
__device__ __half g_att [NTOK * DMODEL];
__device__ __half g_gu  [NTOK * DFF];
__device__ float  g_kvp [16 * KCH2 * 64 * 64];
__device__ float  g_zp  [16 * KCH2 * 64];
__device__ __half g_kvh [16 * 64 * 64];
__device__ float  g_z   [16 * 64];
__device__ float  g_xm  [BATCH * DMODEL];
// converted fp16 weights, row-major [K, N]
__device__ __half g_WqkvH[DMODEL * 768];
__device__ __half g_WphiH[DHEAD * MFEAT];
__device__ __half g_WoH  [DMODEL * DMODEL];
__device__ __half g_WguH [DMODEL * (2*DFF)];
__device__ __half g_WdH  [DFF * DMODEL];

struct alignas(8) half4 { __half2 a, b; };
__device__ __forceinline__ half4 f4_to_h4(float4 v) {
    half4 r; r.a = __floats2half2_rn(v.x, v.y); r.b = __floats2half2_rn(v.z, v.w); return r;
}

// ---------------- single merged weight conversion ----------------
#define CQKV 393216
#define CGU  2097152
#define CPHI 4096
#define CWO  262144
#define CWD  1048576
#define CTOT (CQKV + CGU + CPHI + CWO + CWD)

__global__ void conv_all(const float* __restrict__ Wq, const float* __restrict__ Wk,
                         const float* __restrict__ Wv, const float* __restrict__ Wg,
                         const float* __restrict__ Wu, const float* __restrict__ Wphi,
                         const float* __restrict__ Wo, const float* __restrict__ Wd,
                         __half* __restrict__ WqkvH, __half* __restrict__ WguH,
                         __half* __restrict__ WphiH, __half* __restrict__ WoH,
                         __half* __restrict__ WdH)
{
    int idx = blockIdx.x * 256 + threadIdx.x;
    if (idx < CQKV) {
        int r = idx / 768, c = idx % 768;
        float v = (c < 512) ? Wq[r * 512 + c]
                            : (c < 640 ? Wk[r * 128 + c - 512] : Wv[r * 128 + c - 640]);
        WqkvH[idx] = __float2half(v);
        return;
    }
    idx -= CQKV;
    if (idx < CGU) {
        int r = idx >> 12, c = idx & 4095;
        int j = c >> 1;
        float v = (c & 1) ? Wu[r * DFF + j] : Wg[r * DFF + j];
        WguH[idx] = __float2half(v);
        return;
    }
    idx -= CGU;
    if (idx < CPHI) { WphiH[idx] = __float2half(Wphi[idx]); return; }
    idx -= CPHI;
    if (idx < CWO)  { WoH[idx]   = __float2half(Wo[idx]);   return; }
    idx -= CWO;
    if (idx < CWD)  { WdH[idx]   = __float2half(Wd[idx]);   return; }
}

// ---------------- fp16 WMMA GEMM: 128 thr, 64x64 warp tile, 4 stages ----------------
#define EPI_QKV    0
#define EPI_EXPABS 1
#define EPI_RES    2   // fp16 out = acc + X(fp16), smem-staged
#define EPI_SWIGLU 3
#define STAGES 4
#define NTHR   128

template<int BN, int EPI>
__global__ __launch_bounds__(NTHR, 3) void gemm_h(
    const __half* __restrict__ A, const __half* __restrict__ B,
    void* __restrict__ Cout, const __half* __restrict__ X,
    int M, int K, int Nc)
{
    constexpr int BM = 128, BK = 32;
    constexpr int LDA_S = BK + 8;
    constexpr int LDB_S = BN + 8;
    constexpr int LDC_S = BN + 4;
    constexpr int MI = 4;
    constexpr int NJ = BN / 32;
    constexpr int A_ELE = BM * LDA_S;
    constexpr int B_ELE = BK * LDB_S;
    constexpr int STG_ELE = A_ELE + B_ELE;

    extern __shared__ __align__(16) char smem_raw[];
    __half* stg = (__half*)smem_raw;

    const int tid  = threadIdx.x;
    const int bm   = blockIdx.y * BM;
    const int bn   = blockIdx.x * BN;
    const int warp = tid >> 5;
    const int wm   = (warp & 1) * 64;
    const int wn   = (warp >> 1) * (BN / 2);

    wmma::fragment<wmma::accumulator, 16, 16, 16, float> c[MI][NJ];
#pragma unroll
    for (int i = 0; i < MI; i++)
#pragma unroll
        for (int j = 0; j < NJ; j++) wmma::fill_fragment(c[i][j], 0.0f);

    const int nK = K / BK;

    auto load_stage = [&](int kt, int s) {
        __half* As = stg + s * STG_ELE;
        __half* Bs = As + A_ELE;
#pragma unroll
        for (int i = 0; i < 4; i++) {
            int idx = tid + i * NTHR;
            int r  = idx >> 2;
            int cc = (idx & 3) * 8;
            __pipeline_memcpy_async(&As[r * LDA_S + cc],
                                    &A[(size_t)(bm + r) * K + kt + cc], 16);
        }
        constexpr int CH = BN / 8;
        constexpr int NB = (BK * CH) / NTHR;
#pragma unroll
        for (int i = 0; i < NB; i++) {
            int idx = tid + i * NTHR;
            int r  = idx / CH;
            int cc = (idx % CH) * 8;
            __pipeline_memcpy_async(&Bs[r * LDB_S + cc],
                                    &B[(size_t)(kt + r) * Nc + bn + cc], 16);
        }
    };

#pragma unroll
    for (int s = 0; s < STAGES - 1; s++) {
        if (s < nK) load_stage(s * BK, s);
        __pipeline_commit();
    }

    for (int kt_i = 0; kt_i < nK; kt_i++) {
        __pipeline_wait_prior(STAGES - 2);
        __syncthreads();
        int ldk = kt_i + STAGES - 1;
        if (ldk < nK) load_stage(ldk * BK, ldk % STAGES);
        __pipeline_commit();

        int s = kt_i % STAGES;
        __half* As = stg + s * STG_ELE;
        __half* Bs = As + A_ELE;
#pragma unroll
        for (int kk = 0; kk < BK; kk += 16) {
            wmma::fragment<wmma::matrix_a, 16, 16, 16, __half, wmma::row_major> a[MI];
            wmma::fragment<wmma::matrix_b, 16, 16, 16, __half, wmma::row_major> b[NJ];
#pragma unroll
            for (int i = 0; i < MI; i++)
                wmma::load_matrix_sync(a[i], &As[(wm + i * 16) * LDA_S + kk], LDA_S);
#pragma unroll
            for (int j = 0; j < NJ; j++)
                wmma::load_matrix_sync(b[j], &Bs[kk * LDB_S + wn + j * 16], LDB_S);
#pragma unroll
            for (int i = 0; i < MI; i++)
#pragma unroll
                for (int j = 0; j < NJ; j++)
                    wmma::mma_sync(c[i][j], a[i], b[j], c[i][j]);
        }
    }

    // ---- epilogue ----
    if (EPI == EPI_SWIGLU || EPI == EPI_RES) {
        // smem-staged, two 64-row passes
        __syncthreads();
        float* Cs = (float*)smem_raw;
        constexpr int F4R = BN / 4;
        constexpr int NIT = (64 * F4R) / NTHR;
#pragma unroll
        for (int hrow = 0; hrow < 2; hrow++) {
            __syncthreads();
            if ((wm >> 6) == hrow) {
#pragma unroll
                for (int i = 0; i < MI; i++)
#pragma unroll
                    for (int j = 0; j < NJ; j++)
                        wmma::store_matrix_sync(&Cs[((wm & 63) + i * 16) * LDC_S + wn + j * 16],
                                                c[i][j], LDC_S, wmma::mem_row_major);
            }
            __syncthreads();
#pragma unroll
            for (int i = 0; i < NIT; i++) {
                int e  = tid + i * NTHR;
                int r  = e / F4R;
                int cc = (e % F4R) * 4;
                float4 vv = *(float4*)&Cs[r * LDC_S + cc];
                int grow = bm + hrow * 64 + r;
                if (EPI == EPI_RES) {
                    size_t gidx = (size_t)grow * Nc + bn + cc;
                    half4 xh = *(const half4*)&X[gidx];
                    float2 x0 = __half22float2(xh.a);
                    float2 x1 = __half22float2(xh.b);
                    vv.x += x0.x; vv.y += x0.y; vv.z += x1.x; vv.w += x1.y;
                    *(half4*)&((__half*)Cout)[gidx] = f4_to_h4(vv);
                } else {
                    float s0 = vv.x / (1.0f + expf(-vv.x)) * vv.y;
                    float s1 = vv.z / (1.0f + expf(-vv.z)) * vv.w;
                    int jo = (bn + cc) >> 1;
                    *(__half2*)&((__half*)Cout)[(size_t)grow * (Nc >> 1) + jo] =
                        __floats2half2_rn(s0, s1);
                }
            }
        }
    } else {
        // fragment-direct epilogues (QKV / EXPABS)
#pragma unroll
        for (int i = 0; i < MI; i++) {
#pragma unroll
            for (int j = 0; j < NJ; j++) {
                int grow = bm + wm + i * 16;
                int gcol = bn + wn + j * 16;
                wmma::fragment<wmma::accumulator, 16, 16, 16, __half> ch;
#pragma unroll
                for (int t = 0; t < ch.num_elements; t++) {
                    float v = c[i][j].x[t];
                    if (EPI == EPI_EXPABS) v = expf(-fabsf(v));
                    ch.x[t] = __float2half(v);
                }
                __half* dst; int ld, c0;
                if (EPI == EPI_QKV) {
                    if (gcol < 512)      { dst = (__half*)Cout;                    ld = 512; c0 = gcol; }
                    else if (gcol < 640) { dst = (__half*)Cout + (size_t)M * 512;  ld = 128; c0 = gcol - 512; }
                    else                 { dst = (__half*)Cout + (size_t)M * 640;  ld = 128; c0 = gcol - 640; }
                } else {
                    dst = (__half*)Cout; ld = Nc; c0 = gcol;
                }
                wmma::store_matrix_sync(dst + (size_t)grow * ld + c0, ch, ld,
                                        wmma::mem_row_major);
            }
        }
    }
}

// ---------------- gather + rmsnorm (fp16 x) ----------------
__global__ __launch_bounds__(128) void gather_rmsnorm_kernel(
    const int* __restrict__ ids, const float* __restrict__ emb,
    const __half* __restrict__ xin, const float* __restrict__ g,
    __half* __restrict__ xout, __half* __restrict__ h)
{
    int token = blockIdx.x;
    int c = threadIdx.x * 4;
    float4 v;
    if (ids) {
        v = *(const float4*)&emb[(size_t)ids[token] * DMODEL + c];
    } else {
        half4 xh = *(const half4*)&xin[(size_t)token * DMODEL + c];
        float2 a = __half22float2(xh.a), b = __half22float2(xh.b);
        v.x = a.x; v.y = a.y; v.z = b.x; v.w = b.y;
    }
    float ss = v.x * v.x + v.y * v.y + v.z * v.z + v.w * v.w;
#pragma unroll
    for (int off = 16; off > 0; off >>= 1) ss += __shfl_xor_sync(0xffffffffu, ss, off);
    __shared__ float sred[4];
    int warp = threadIdx.x >> 5, lane = threadIdx.x & 31;
    if (lane == 0) sred[warp] = ss;
    __syncthreads();
    float tot = sred[0] + sred[1] + sred[2] + sred[3];
    float scale = rsqrtf(tot * (1.0f / DMODEL) + EPSV);
    float4 gv = *(const float4*)&g[c];
    float4 o;
    o.x = v.x * scale * gv.x; o.y = v.y * scale * gv.y;
    o.z = v.z * scale * gv.z; o.w = v.w * scale * gv.w;
    if (xout) *(half4*)&xout[(size_t)token * DMODEL + c] = f4_to_h4(v);
    *(half4*)&h[(size_t)token * DMODEL + c] = f4_to_h4(o);
}

// ---------------- tensor-core kv partials: kv = pk^T @ v over 512-token chunks ------
__global__ __launch_bounds__(128) void kv_partial_tc(
    const __half* __restrict__ pk, const __half* __restrict__ v,
    float* __restrict__ kvp, float* __restrict__ zp)
{
    int pair = blockIdx.x, chunk = blockIdx.y;
    int b = pair >> 1, kh = pair & 1;
    const int tid = threadIdx.x, w = tid >> 5;
    const int wm = (w & 1) * 32, wn = (w >> 1) * 32;
    const size_t base = (size_t)(b * SEQ + chunk * 512) * 128 + kh * 64;
    const __half* Ap = pk + base;   // col_major (m,s): Ap[s*128 + m]
    const __half* Bp = v  + base;   // row_major (s,d): Bp[s*128 + d]

    wmma::fragment<wmma::accumulator, 16, 16, 16, float> c[2][2];
#pragma unroll
    for (int i = 0; i < 2; i++)
#pragma unroll
        for (int j = 0; j < 2; j++) wmma::fill_fragment(c[i][j], 0.0f);

    for (int k = 0; k < 512; k += 16) {
        wmma::fragment<wmma::matrix_a, 16, 16, 16, __half, wmma::col_major> a[2];
        wmma::fragment<wmma::matrix_b, 16, 16, 16, __half, wmma::row_major> bb[2];
#pragma unroll
        for (int i = 0; i < 2; i++)
            wmma::load_matrix_sync(a[i], Ap + (size_t)k * 128 + wm + i * 16, 128);
#pragma unroll
        for (int j = 0; j < 2; j++)
            wmma::load_matrix_sync(bb[j], Bp + (size_t)k * 128 + wn + j * 16, 128);
#pragma unroll
        for (int i = 0; i < 2; i++)
#pragma unroll
            for (int j = 0; j < 2; j++)
                wmma::mma_sync(c[i][j], a[i], bb[j], c[i][j]);
    }
    float* o = kvp + ((size_t)pair * KCH2 + chunk) * 4096;
#pragma unroll
    for (int i = 0; i < 2; i++)
#pragma unroll
        for (int j = 0; j < 2; j++)
            wmma::store_matrix_sync(o + (wm + i * 16) * 64 + wn + j * 16, c[i][j], 64,
                                    wmma::mem_row_major);
    // z partial: column sums of pk over this chunk
    __shared__ float zs[2][64];
    int m = tid & 63, hf = tid >> 6;
    float s = 0.f;
    for (int t = hf * 256; t < hf * 256 + 256; t++)
        s += __half2float(Ap[(size_t)t * 128 + m]);
    zs[hf][m] = s;
    __syncthreads();
    if (tid < 64)
        zp[(pair * KCH2 + chunk) * 64 + tid] = zs[0][tid] + zs[1][tid];
}

// ---------------- kv reduce -> fp16 kv_d + fp32 z ----------------
__global__ __launch_bounds__(256) void kv_reduce_kernel(
    const float* __restrict__ kvp, const float* __restrict__ zp,
    __half* __restrict__ kvh, float* __restrict__ z)
{
    int pair = blockIdx.x, seg = blockIdx.y;     // grid (16, 4), 1024 elems per seg
    int lo = seg * 1024;
    for (int idx = lo + threadIdx.x; idx < lo + 1024; idx += 256) {
        float s = 0.f;
#pragma unroll
        for (int c = 0; c < KCH2; c++)
            s += kvp[((size_t)pair * KCH2 + c) * 4096 + idx];
        kvh[(size_t)pair * 4096 + idx] = __float2half(s);
    }
    if (seg == 0 && threadIdx.x < 64) {
        float s = 0.f;
#pragma unroll
        for (int c = 0; c < KCH2; c++)
            s += zp[(pair * KCH2 + c) * 64 + threadIdx.x];
        z[pair * 64 + threadIdx.x] = s;
    }
}

// ---------------- tensor-core num + fp32 den -> attn ----------------
__global__ __launch_bounds__(128) void numden_tc_kernel(
    const __half* __restrict__ pq, const __half* __restrict__ kvh,
    const float* __restrict__ zg, __half* __restrict__ att)
{
    __shared__ __half kvs[64 * 72];
    __shared__ float  zs[64];
    __shared__ float  Cs[128 * 68];

    const int tid  = threadIdx.x;
    const int h    = blockIdx.y;
    const int kh   = h >> 2;
    const int tok0 = blockIdx.x * 128;
    const int pair = (tok0 >> 13) * 2 + kh;

#pragma unroll
    for (int i = 0; i < 4; i++) {
        int e = tid + i * 128;
        int r = e >> 3, c8 = (e & 7) * 8;
        *(uint4*)&kvs[r * 72 + c8] = *(const uint4*)&kvh[(size_t)pair * 4096 + r * 64 + c8];
    }
    if (tid < 64) zs[tid] = zg[pair * 64 + tid];
    __syncthreads();

    const int warp = tid >> 5;
    wmma::fragment<wmma::accumulator, 16, 16, 16, float> c[2][4];
#pragma unroll
    for (int i = 0; i < 2; i++)
#pragma unroll
        for (int j = 0; j < 4; j++) wmma::fill_fragment(c[i][j], 0.0f);

    const __half* Abase = pq + (size_t)(tok0 + warp * 32) * 512 + h * 64;
#pragma unroll
    for (int kk = 0; kk < 64; kk += 16) {
        wmma::fragment<wmma::matrix_a, 16, 16, 16, __half, wmma::row_major> a[2];
        wmma::fragment<wmma::matrix_b, 16, 16, 16, __half, wmma::row_major> b[4];
#pragma unroll
        for (int i = 0; i < 2; i++)
            wmma::load_matrix_sync(a[i], Abase + (size_t)i * 16 * 512 + kk, 512);
#pragma unroll
        for (int j = 0; j < 4; j++)
            wmma::load_matrix_sync(b[j], &kvs[kk * 72 + j * 16], 72);
#pragma unroll
        for (int i = 0; i < 2; i++)
#pragma unroll
            for (int j = 0; j < 4; j++)
                wmma::mma_sync(c[i][j], a[i], b[j], c[i][j]);
    }
#pragma unroll
    for (int i = 0; i < 2; i++)
#pragma unroll
        for (int j = 0; j < 4; j++)
            wmma::store_matrix_sync(&Cs[(warp * 32 + i * 16) * 68 + j * 16],
                                    c[i][j], 68, wmma::mem_row_major);

    const __half* prow = pq + (size_t)(tok0 + tid) * 512 + h * 64;
    float den = 0.f;
#pragma unroll
    for (int m = 0; m < 64; m += 2) {
        float2 pf = __half22float2(*(const __half2*)(prow + m));
        den = fmaf(pf.x, zs[m], den);
        den = fmaf(pf.y, zs[m + 1], den);
    }
    __syncwarp();
    float rr = 1.0f / (den + EPSV);
    __half* orow = att + (size_t)(tok0 + tid) * 512 + h * 64;
#pragma unroll
    for (int d = 0; d < 64; d += 4) {
        float4 v = *(float4*)&Cs[tid * 68 + d];
        half4 hv;
        hv.a = __floats2half2_rn(v.x * rr, v.y * rr);
        hv.b = __floats2half2_rn(v.z * rr, v.w * rr);
        *(half4*)(orow + d) = hv;
    }
}

// ---------------- pool (fp16 in) + head ----------------
__global__ __launch_bounds__(256) void pool_kernel(
    const __half* __restrict__ x, float* __restrict__ xm)
{
    int b = blockIdx.y;
    int c = blockIdx.x * 64 + (threadIdx.x & 63);
    int part = threadIdx.x >> 6;
    float s = 0.f;
    for (int t = part; t < SEQ; t += 4)
        s += __half2float(x[((size_t)b * SEQ + t) * DMODEL + c]);
    __shared__ float red[4][64];
    red[part][threadIdx.x & 63] = s;
    __syncthreads();
    if (part == 0) {
        int l = threadIdx.x & 63;
        xm[b * DMODEL + c] = red[0][l] + red[1][l] + red[2][l] + red[3][l];
    }
}

__global__ __launch_bounds__(512) void head_kernel(
    const float* __restrict__ xm, const float* __restrict__ Wc,
    const float* __restrict__ bc, float* __restrict__ out)
{
    int warp = threadIdx.x >> 5, lane = threadIdx.x & 31;
    int b = warp >> 1, cls = warp & 1;
    float s = 0.f;
    for (int d = lane; d < DMODEL; d += 32)
        s += xm[b * DMODEL + d] * Wc[d * NCLS + cls];
#pragma unroll
    for (int off = 16; off > 0; off >>= 1) s += __shfl_xor_sync(0xffffffffu, s, off);
    if (lane == 0) out[b * NCLS + cls] = s * (1.0f / SEQ) + bc[cls];
}

// ---------------- launch ----------------
#define SMEM_BN128_V (STAGES * (128 * 40 + 32 * 136) * 2)   // 75776
#define SMEM_BN64_V  (STAGES * (128 * 40 + 32 * 72) * 2)    // 59392

extern "C" void kernel_launch(void* const* d_in, const int* in_sizes, int n_in,
                              void* d_out, int out_size)
{
    (void)in_sizes; (void)n_in; (void)out_size;
    const int*   ids  = (const int*)  d_in[0];
    const float* emb  = (const float*)d_in[1];
    const float* Wq   = (const float*)d_in[2];
    const float* Wk   = (const float*)d_in[3];
    const float* Wv   = (const float*)d_in[4];
    const float* Wphi = (const float*)d_in[5];
    const float* Wo   = (const float*)d_in[6];
    const float* g1   = (const float*)d_in[7];
    const float* g2   = (const float*)d_in[8];
    const float* Wg   = (const float*)d_in[9];
    const float* Wu   = (const float*)d_in[10];
    const float* Wd   = (const float*)d_in[11];
    const float* Wc   = (const float*)d_in[12];
    const float* bc   = (const float*)d_in[13];
    float* out = (float*)d_out;

    float *kvp, *zp, *z, *xm;
    __half *x, *h, *qkv, *pqk, *att, *gu, *kvh;
    __half *WqkvH, *WphiH, *WoH, *WguH, *WdH;
    cudaGetSymbolAddress((void**)&x,    g_x);
    cudaGetSymbolAddress((void**)&h,    g_h);
    cudaGetSymbolAddress((void**)&qkv,  g_qkv);
    cudaGetSymbolAddress((void**)&pqk,  g_pqk);
    cudaGetSymbolAddress((void**)&att,  g_att);
    cudaGetSymbolAddress((void**)&gu,   g_gu);
    cudaGetSymbolAddress((void**)&kvp,  g_kvp);
    cudaGetSymbolAddress((void**)&zp,   g_zp);
    cudaGetSymbolAddress((void**)&kvh,  g_kvh);
    cudaGetSymbolAddress((void**)&z,    g_z);
    cudaGetSymbolAddress((void**)&xm,   g_xm);
    cudaGetSymbolAddress((void**)&WqkvH, g_WqkvH);
    cudaGetSymbolAddress((void**)&WphiH, g_WphiH);
    cudaGetSymbolAddress((void**)&WoH,   g_WoH);
    cudaGetSymbolAddress((void**)&WguH,  g_WguH);
    cudaGetSymbolAddress((void**)&WdH,   g_WdH);

    cudaFuncSetAttribute(gemm_h<128, EPI_QKV>,    cudaFuncAttributeMaxDynamicSharedMemorySize, SMEM_BN128_V);
    cudaFuncSetAttribute(gemm_h<128, EPI_RES>,    cudaFuncAttributeMaxDynamicSharedMemorySize, SMEM_BN128_V);
    cudaFuncSetAttribute(gemm_h<128, EPI_SWIGLU>, cudaFuncAttributeMaxDynamicSharedMemorySize, SMEM_BN128_V);
    cudaFuncSetAttribute(gemm_h<64,  EPI_EXPABS>, cudaFuncAttributeMaxDynamicSharedMemorySize, SMEM_BN64_V);

    // 1. merged weight conversion
    conv_all<<<(CTOT + 255) / 256, 256>>>(Wq, Wk, Wv, Wg, Wu, Wphi, Wo, Wd,
                                          WqkvH, WguH, WphiH, WoH, WdH);

    // 2. embedding gather + rmsnorm (x fp16)
    gather_rmsnorm_kernel<<<NTOK, 128>>>(ids, emb, nullptr, g1, x, h);

    // 3. fused qkv projection
    {
        dim3 grid(768 / 128, NTOK / 128);
        gemm_h<128, EPI_QKV><<<grid, NTHR, SMEM_BN128_V>>>(h, WqkvH, qkv, nullptr, NTOK, DMODEL, 768);
    }

    // 4. single Laplacian feature-map GEMM over q-rows + k-rows
    {
        dim3 grid(1, NTOK * (NHEAD + NKV) / 128);
        gemm_h<64, EPI_EXPABS><<<grid, NTHR, SMEM_BN64_V>>>(
            qkv, WphiH, pqk, nullptr, NTOK * (NHEAD + NKV), DHEAD, MFEAT);
    }

    // 5. tensor-core kv partials + reduce
    {
        dim3 gp(BATCH * NKV, KCH2);
        kv_partial_tc<<<gp, 128>>>(pqk + (size_t)NTOK * NHEAD * MFEAT,
                                   qkv + (size_t)NTOK * 640, kvp, zp);
        dim3 gr(BATCH * NKV, 4);
        kv_reduce_kernel<<<gr, 256>>>(kvp, zp, kvh, z);
    }

    // 6. tensor-core num + fp32 den -> attn
    {
        dim3 gn(NTOK / 128, NHEAD);
        numden_tc_kernel<<<gn, 128>>>(pqk, kvh, z, att);
    }

    // 7. output projection + residual (fp16 x)
    {
        dim3 grid(DMODEL / 128, NTOK / 128);
        gemm_h<128, EPI_RES><<<grid, NTHR, SMEM_BN128_V>>>(att, WoH, x, x, NTOK, DMODEL, DMODEL);
    }

    // 8. pre-FFN rmsnorm (reads fp16 x)
    gather_rmsnorm_kernel<<<NTOK, 128>>>(nullptr, nullptr, x, g2, nullptr, h);

    // 9. fused SwiGLU up
    {
        dim3 grid(4096 / 128, NTOK / 128);
        gemm_h<128, EPI_SWIGLU><<<grid, NTHR, SMEM_BN128_V>>>(h, WguH, gu, nullptr, NTOK, DMODEL, 4096);
    }
    // 10. down proj + residual (fp16 x)
    {
        dim3 grid(DMODEL / 128, NTOK / 128);
        gemm_h<128, EPI_RES><<<grid, NTHR, SMEM_BN128_V>>>(gu, WdH, x, x, NTOK, DFF, DMODEL);
    }

    // 11. mean pool + head
    {
        dim3 gpool(DMODEL / 64, BATCH);
        pool_kernel<<<gpool, 256>>>(x, xm);
    }
    head_kernel<<<1, 512>>>(xm, Wc, bc, out);
}

// round 16
// speedup vs baseline: 1.4786x; 1.0496x over previous
#include <cuda_runtime.h>
#include <cuda_fp16.h>
#include <cuda_pipeline.h>
#include <mma.h>
#include <math.h>
#include <cstdint>

using namespace nvcuda;

// ---------------- problem constants ----------------
#define NTOK   65536
#define BATCH  8
#define SEQ    8192
#define DMODEL 512
#define NHEAD  8
#define NKV    2
#define DHEAD  64
#define MFEAT  64
#define DFF    2048
#define NCLS   2
#define EPSV   1e-6f
#define KCH2   16          // kv chunks of 512 tokens

// ---------------- scratch ----------------
__device__ __half g_x   [NTOK * DMODEL];          // fp16 residual stream
__device__ __half g_h   [NTOK * DMODEL];
__device__ __half g_qkv [NTOK * (DMODEL + 2*128)];   // q | k | v contiguous
__device__ __half g_pqk [NTOK * (NHEAD + NKV) * MFEAT];
__device__ __half g_att [NTOK * DMODEL];
__device__ __half g_gu  [NTOK * DFF];
__device__ float  g_kvp [16 * KCH2 * 64 * 64];
__device__ float  g_zp  [16 * KCH2 * 64];
__device__ __half g_kvh [16 * 64 * 64];
__device__ float  g_z   [16 * 64];
__device__ float  g_poolp[512 * 4 * 128];         // per (mtile, ntile) col sums
__device__ float  g_xm  [BATCH * DMODEL];
// converted fp16 weights, row-major [K, N]
__device__ __half g_WqkvH[DMODEL * 768];
__device__ __half g_WphiH[DHEAD * MFEAT];
__device__ __half g_WoH  [DMODEL * DMODEL];
__device__ __half g_WguH [DMODEL * (2*DFF)];
__device__ __half g_WdH  [DFF * DMODEL];

struct alignas(8) half4 { __half2 a, b; };
__device__ __forceinline__ half4 f4_to_h4(float4 v) {
    half4 r; r.a = __floats2half2_rn(v.x, v.y); r.b = __floats2half2_rn(v.z, v.w); return r;
}

// ---------------- single merged weight conversion ----------------
#define CQKV 393216
#define CGU  2097152
#define CPHI 4096
#define CWO  262144
#define CWD  1048576
#define CTOT (CQKV + CGU + CPHI + CWO + CWD)

__global__ void conv_all(const float* __restrict__ Wq, const float* __restrict__ Wk,
                         const float* __restrict__ Wv, const float* __restrict__ Wg,
                         const float* __restrict__ Wu, const float* __restrict__ Wphi,
                         const float* __restrict__ Wo, const float* __restrict__ Wd,
                         __half* __restrict__ WqkvH, __half* __restrict__ WguH,
                         __half* __restrict__ WphiH, __half* __restrict__ WoH,
                         __half* __restrict__ WdH)
{
    int idx = blockIdx.x * 256 + threadIdx.x;
    if (idx < CQKV) {
        int r = idx / 768, c = idx % 768;
        float v = (c < 512) ? Wq[r * 512 + c]
                            : (c < 640 ? Wk[r * 128 + c - 512] : Wv[r * 128 + c - 640]);
        WqkvH[idx] = __float2half(v);
        return;
    }
    idx -= CQKV;
    if (idx < CGU) {
        int r = idx >> 12, c = idx & 4095;
        int j = c >> 1;
        float v = (c & 1) ? Wu[r * DFF + j] : Wg[r * DFF + j];
        WguH[idx] = __float2half(v);
        return;
    }
    idx -= CGU;
    if (idx < CPHI) { WphiH[idx] = __float2half(Wphi[idx]); return; }
    idx -= CPHI;
    if (idx < CWO)  { WoH[idx]   = __float2half(Wo[idx]);   return; }
    idx -= CWO;
    if (idx < CWD)  { WdH[idx]   = __float2half(Wd[idx]);   return; }
}

// ---------------- fp16 WMMA GEMM: 128 thr, 64x64 warp tile, 4 stages ----------------
#define EPI_QKV     0
#define EPI_EXPABS  1
#define EPI_RES     2   // fp16 out = acc + X(fp16), smem-staged
#define EPI_SWIGLU  3
#define EPI_RESPOOL 4   // like RES but emits column-sum partials instead of x
#define STAGES 4
#define NTHR   128

template<int BN, int EPI>
__global__ __launch_bounds__(NTHR, 3) void gemm_h(
    const __half* __restrict__ A, const __half* __restrict__ B,
    void* __restrict__ Cout, const __half* __restrict__ X,
    int M, int K, int Nc)
{
    constexpr int BM = 128, BK = 32;
    constexpr int LDA_S = BK + 8;
    constexpr int LDB_S = BN + 8;
    constexpr int LDC_S = BN + 4;
    constexpr int MI = 4;
    constexpr int NJ = BN / 32;
    constexpr int A_ELE = BM * LDA_S;
    constexpr int B_ELE = BK * LDB_S;
    constexpr int STG_ELE = A_ELE + B_ELE;

    extern __shared__ __align__(16) char smem_raw[];
    __half* stg = (__half*)smem_raw;

    const int tid  = threadIdx.x;
    const int bm   = blockIdx.y * BM;
    const int bn   = blockIdx.x * BN;
    const int warp = tid >> 5;
    const int wm   = (warp & 1) * 64;
    const int wn   = (warp >> 1) * (BN / 2);

    wmma::fragment<wmma::accumulator, 16, 16, 16, float> c[MI][NJ];
#pragma unroll
    for (int i = 0; i < MI; i++)
#pragma unroll
        for (int j = 0; j < NJ; j++) wmma::fill_fragment(c[i][j], 0.0f);

    const int nK = K / BK;

    auto load_stage = [&](int kt, int s) {
        __half* As = stg + s * STG_ELE;
        __half* Bs = As + A_ELE;
#pragma unroll
        for (int i = 0; i < 4; i++) {
            int idx = tid + i * NTHR;
            int r  = idx >> 2;
            int cc = (idx & 3) * 8;
            __pipeline_memcpy_async(&As[r * LDA_S + cc],
                                    &A[(size_t)(bm + r) * K + kt + cc], 16);
        }
        constexpr int CH = BN / 8;
        constexpr int NB = (BK * CH) / NTHR;
#pragma unroll
        for (int i = 0; i < NB; i++) {
            int idx = tid + i * NTHR;
            int r  = idx / CH;
            int cc = (idx % CH) * 8;
            __pipeline_memcpy_async(&Bs[r * LDB_S + cc],
                                    &B[(size_t)(kt + r) * Nc + bn + cc], 16);
        }
    };

#pragma unroll
    for (int s = 0; s < STAGES - 1; s++) {
        if (s < nK) load_stage(s * BK, s);
        __pipeline_commit();
    }

    for (int kt_i = 0; kt_i < nK; kt_i++) {
        __pipeline_wait_prior(STAGES - 2);
        __syncthreads();
        int ldk = kt_i + STAGES - 1;
        if (ldk < nK) load_stage(ldk * BK, ldk % STAGES);
        __pipeline_commit();

        int s = kt_i % STAGES;
        __half* As = stg + s * STG_ELE;
        __half* Bs = As + A_ELE;
#pragma unroll
        for (int kk = 0; kk < BK; kk += 16) {
            wmma::fragment<wmma::matrix_a, 16, 16, 16, __half, wmma::row_major> a[MI];
            wmma::fragment<wmma::matrix_b, 16, 16, 16, __half, wmma::row_major> b[NJ];
#pragma unroll
            for (int i = 0; i < MI; i++)
                wmma::load_matrix_sync(a[i], &As[(wm + i * 16) * LDA_S + kk], LDA_S);
#pragma unroll
            for (int j = 0; j < NJ; j++)
                wmma::load_matrix_sync(b[j], &Bs[kk * LDB_S + wn + j * 16], LDB_S);
#pragma unroll
            for (int i = 0; i < MI; i++)
#pragma unroll
                for (int j = 0; j < NJ; j++)
                    wmma::mma_sync(c[i][j], a[i], b[j], c[i][j]);
        }
    }

    // ---- epilogue ----
    if (EPI == EPI_SWIGLU || EPI == EPI_RES || EPI == EPI_RESPOOL) {
        // smem-staged, two 64-row passes
        __syncthreads();
        float* Cs = (float*)smem_raw;
        float* SP = (float*)(smem_raw + 64 * LDC_S * 4);   // pool partials [4][BN]
        constexpr int F4R = BN / 4;
        constexpr int NIT = (64 * F4R) / NTHR;
        float psum[4] = {0.f, 0.f, 0.f, 0.f};
#pragma unroll
        for (int hrow = 0; hrow < 2; hrow++) {
            __syncthreads();
            if ((wm >> 6) == hrow) {
#pragma unroll
                for (int i = 0; i < MI; i++)
#pragma unroll
                    for (int j = 0; j < NJ; j++)
                        wmma::store_matrix_sync(&Cs[((wm & 63) + i * 16) * LDC_S + wn + j * 16],
                                                c[i][j], LDC_S, wmma::mem_row_major);
            }
            __syncthreads();
#pragma unroll
            for (int i = 0; i < NIT; i++) {
                int e  = tid + i * NTHR;
                int r  = e / F4R;
                int cc = (e % F4R) * 4;
                float4 vv = *(float4*)&Cs[r * LDC_S + cc];
                int grow = bm + hrow * 64 + r;
                if (EPI == EPI_RES || EPI == EPI_RESPOOL) {
                    size_t gidx = (size_t)grow * Nc + bn + cc;
                    half4 xh = *(const half4*)&X[gidx];
                    float2 x0 = __half22float2(xh.a);
                    float2 x1 = __half22float2(xh.b);
                    vv.x += x0.x; vv.y += x0.y; vv.z += x1.x; vv.w += x1.y;
                    if (EPI == EPI_RES) {
                        *(half4*)&((__half*)Cout)[gidx] = f4_to_h4(vv);
                    } else {
                        psum[0] += vv.x; psum[1] += vv.y;
                        psum[2] += vv.z; psum[3] += vv.w;
                    }
                } else {
                    float s0 = vv.x / (1.0f + expf(-vv.x)) * vv.y;
                    float s1 = vv.z / (1.0f + expf(-vv.z)) * vv.w;
                    int jo = (bn + cc) >> 1;
                    *(__half2*)&((__half*)Cout)[(size_t)grow * (Nc >> 1) + jo] =
                        __floats2half2_rn(s0, s1);
                }
            }
        }
        if (EPI == EPI_RESPOOL) {
            // cc = (tid%F4R)*4 is invariant: 4-group reduction over tid/F4R
            int grp = tid / F4R, col4 = tid % F4R;
            __syncthreads();
#pragma unroll
            for (int k = 0; k < 4; k++) SP[grp * BN + col4 * 4 + k] = psum[k];
            __syncthreads();
            if (tid < BN) {
                float s = SP[tid] + SP[BN + tid] + SP[2 * BN + tid] + SP[3 * BN + tid];
                ((float*)Cout)[((size_t)blockIdx.y * gridDim.x + blockIdx.x) * BN + tid] = s;
            }
        }
    } else {
        // fragment-direct epilogues (QKV / EXPABS)
#pragma unroll
        for (int i = 0; i < MI; i++) {
#pragma unroll
            for (int j = 0; j < NJ; j++) {
                int grow = bm + wm + i * 16;
                int gcol = bn + wn + j * 16;
                wmma::fragment<wmma::accumulator, 16, 16, 16, __half> ch;
#pragma unroll
                for (int t = 0; t < ch.num_elements; t++) {
                    float v = c[i][j].x[t];
                    if (EPI == EPI_EXPABS) v = expf(-fabsf(v));
                    ch.x[t] = __float2half(v);
                }
                __half* dst; int ld, c0;
                if (EPI == EPI_QKV) {
                    if (gcol < 512)      { dst = (__half*)Cout;                    ld = 512; c0 = gcol; }
                    else if (gcol < 640) { dst = (__half*)Cout + (size_t)M * 512;  ld = 128; c0 = gcol - 512; }
                    else                 { dst = (__half*)Cout + (size_t)M * 640;  ld = 128; c0 = gcol - 640; }
                } else {
                    dst = (__half*)Cout; ld = Nc; c0 = gcol;
                }
                wmma::store_matrix_sync(dst + (size_t)grow * ld + c0, ch, ld,
                                        wmma::mem_row_major);
            }
        }
    }
}

// ---------------- gather + rmsnorm (fp16 x) ----------------
__global__ __launch_bounds__(128) void gather_rmsnorm_kernel(
    const int* __restrict__ ids, const float* __restrict__ emb,
    const __half* __restrict__ xin, const float* __restrict__ g,
    __half* __restrict__ xout, __half* __restrict__ h)
{
    int token = blockIdx.x;
    int c = threadIdx.x * 4;
    float4 v;
    if (ids) {
        v = *(const float4*)&emb[(size_t)ids[token] * DMODEL + c];
    } else {
        half4 xh = *(const half4*)&xin[(size_t)token * DMODEL + c];
        float2 a = __half22float2(xh.a), b = __half22float2(xh.b);
        v.x = a.x; v.y = a.y; v.z = b.x; v.w = b.y;
    }
    float ss = v.x * v.x + v.y * v.y + v.z * v.z + v.w * v.w;
#pragma unroll
    for (int off = 16; off > 0; off >>= 1) ss += __shfl_xor_sync(0xffffffffu, ss, off);
    __shared__ float sred[4];
    int warp = threadIdx.x >> 5, lane = threadIdx.x & 31;
    if (lane == 0) sred[warp] = ss;
    __syncthreads();
    float tot = sred[0] + sred[1] + sred[2] + sred[3];
    float scale = rsqrtf(tot * (1.0f / DMODEL) + EPSV);
    float4 gv = *(const float4*)&g[c];
    float4 o;
    o.x = v.x * scale * gv.x; o.y = v.y * scale * gv.y;
    o.z = v.z * scale * gv.z; o.w = v.w * scale * gv.w;
    if (xout) *(half4*)&xout[(size_t)token * DMODEL + c] = f4_to_h4(v);
    *(half4*)&h[(size_t)token * DMODEL + c] = f4_to_h4(o);
}

// ---------------- tensor-core kv partials ----------------
__global__ __launch_bounds__(128) void kv_partial_tc(
    const __half* __restrict__ pk, const __half* __restrict__ v,
    float* __restrict__ kvp, float* __restrict__ zp)
{
    int pair = blockIdx.x, chunk = blockIdx.y;
    int b = pair >> 1, kh = pair & 1;
    const int tid = threadIdx.x, w = tid >> 5;
    const int wm = (w & 1) * 32, wn = (w >> 1) * 32;
    const size_t base = (size_t)(b * SEQ + chunk * 512) * 128 + kh * 64;
    const __half* Ap = pk + base;
    const __half* Bp = v  + base;

    wmma::fragment<wmma::accumulator, 16, 16, 16, float> c[2][2];
#pragma unroll
    for (int i = 0; i < 2; i++)
#pragma unroll
        for (int j = 0; j < 2; j++) wmma::fill_fragment(c[i][j], 0.0f);

    for (int k = 0; k < 512; k += 16) {
        wmma::fragment<wmma::matrix_a, 16, 16, 16, __half, wmma::col_major> a[2];
        wmma::fragment<wmma::matrix_b, 16, 16, 16, __half, wmma::row_major> bb[2];
#pragma unroll
        for (int i = 0; i < 2; i++)
            wmma::load_matrix_sync(a[i], Ap + (size_t)k * 128 + wm + i * 16, 128);
#pragma unroll
        for (int j = 0; j < 2; j++)
            wmma::load_matrix_sync(bb[j], Bp + (size_t)k * 128 + wn + j * 16, 128);
#pragma unroll
        for (int i = 0; i < 2; i++)
#pragma unroll
            for (int j = 0; j < 2; j++)
                wmma::mma_sync(c[i][j], a[i], bb[j], c[i][j]);
    }
    float* o = kvp + ((size_t)pair * KCH2 + chunk) * 4096;
#pragma unroll
    for (int i = 0; i < 2; i++)
#pragma unroll
        for (int j = 0; j < 2; j++)
            wmma::store_matrix_sync(o + (wm + i * 16) * 64 + wn + j * 16, c[i][j], 64,
                                    wmma::mem_row_major);
    __shared__ float zs[2][64];
    int m = tid & 63, hf = tid >> 6;
    float s = 0.f;
    for (int t = hf * 256; t < hf * 256 + 256; t++)
        s += __half2float(Ap[(size_t)t * 128 + m]);
    zs[hf][m] = s;
    __syncthreads();
    if (tid < 64)
        zp[(pair * KCH2 + chunk) * 64 + tid] = zs[0][tid] + zs[1][tid];
}

// ---------------- kv reduce -> fp16 kv_d + fp32 z ----------------
__global__ __launch_bounds__(256) void kv_reduce_kernel(
    const float* __restrict__ kvp, const float* __restrict__ zp,
    __half* __restrict__ kvh, float* __restrict__ z)
{
    int pair = blockIdx.x, seg = blockIdx.y;
    int lo = seg * 1024;
    for (int idx = lo + threadIdx.x; idx < lo + 1024; idx += 256) {
        float s = 0.f;
#pragma unroll
        for (int c = 0; c < KCH2; c++)
            s += kvp[((size_t)pair * KCH2 + c) * 4096 + idx];
        kvh[(size_t)pair * 4096 + idx] = __float2half(s);
    }
    if (seg == 0 && threadIdx.x < 64) {
        float s = 0.f;
#pragma unroll
        for (int c = 0; c < KCH2; c++)
            s += zp[(pair * KCH2 + c) * 64 + threadIdx.x];
        z[pair * 64 + threadIdx.x] = s;
    }
}

// ---------------- tensor-core num + fp32 den -> attn ----------------
__global__ __launch_bounds__(128) void numden_tc_kernel(
    const __half* __restrict__ pq, const __half* __restrict__ kvh,
    const float* __restrict__ zg, __half* __restrict__ att)
{
    __shared__ __half kvs[64 * 72];
    __shared__ float  zs[64];
    __shared__ float  Cs[128 * 68];

    const int tid  = threadIdx.x;
    const int h    = blockIdx.y;
    const int kh   = h >> 2;
    const int tok0 = blockIdx.x * 128;
    const int pair = (tok0 >> 13) * 2 + kh;

#pragma unroll
    for (int i = 0; i < 4; i++) {
        int e = tid + i * 128;
        int r = e >> 3, c8 = (e & 7) * 8;
        *(uint4*)&kvs[r * 72 + c8] = *(const uint4*)&kvh[(size_t)pair * 4096 + r * 64 + c8];
    }
    if (tid < 64) zs[tid] = zg[pair * 64 + tid];
    __syncthreads();

    const int warp = tid >> 5;
    wmma::fragment<wmma::accumulator, 16, 16, 16, float> c[2][4];
#pragma unroll
    for (int i = 0; i < 2; i++)
#pragma unroll
        for (int j = 0; j < 4; j++) wmma::fill_fragment(c[i][j], 0.0f);

    const __half* Abase = pq + (size_t)(tok0 + warp * 32) * 512 + h * 64;
#pragma unroll
    for (int kk = 0; kk < 64; kk += 16) {
        wmma::fragment<wmma::matrix_a, 16, 16, 16, __half, wmma::row_major> a[2];
        wmma::fragment<wmma::matrix_b, 16, 16, 16, __half, wmma::row_major> b[4];
#pragma unroll
        for (int i = 0; i < 2; i++)
            wmma::load_matrix_sync(a[i], Abase + (size_t)i * 16 * 512 + kk, 512);
#pragma unroll
        for (int j = 0; j < 4; j++)
            wmma::load_matrix_sync(b[j], &kvs[kk * 72 + j * 16], 72);
#pragma unroll
        for (int i = 0; i < 2; i++)
#pragma unroll
            for (int j = 0; j < 4; j++)
                wmma::mma_sync(c[i][j], a[i], b[j], c[i][j]);
    }
#pragma unroll
    for (int i = 0; i < 2; i++)
#pragma unroll
        for (int j = 0; j < 4; j++)
            wmma::store_matrix_sync(&Cs[(warp * 32 + i * 16) * 68 + j * 16],
                                    c[i][j], 68, wmma::mem_row_major);

    const __half* prow = pq + (size_t)(tok0 + tid) * 512 + h * 64;
    float den = 0.f;
#pragma unroll
    for (int m = 0; m < 64; m += 2) {
        float2 pf = __half22float2(*(const __half2*)(prow + m));
        den = fmaf(pf.x, zs[m], den);
        den = fmaf(pf.y, zs[m + 1], den);
    }
    __syncwarp();
    float rr = 1.0f / (den + EPSV);
    __half* orow = att + (size_t)(tok0 + tid) * 512 + h * 64;
#pragma unroll
    for (int d = 0; d < 64; d += 4) {
        float4 v = *(float4*)&Cs[tid * 68 + d];
        half4 hv;
        hv.a = __floats2half2_rn(v.x * rr, v.y * rr);
        hv.b = __floats2half2_rn(v.z * rr, v.w * rr);
        *(half4*)(orow + d) = hv;
    }
}

// ---------------- pool partial reduce + head ----------------
__global__ __launch_bounds__(512) void poolred_kernel(
    const float* __restrict__ poolp, float* __restrict__ xm)
{
    int b = blockIdx.x;
    int col = threadIdx.x;                 // 0..511
    int nt = col >> 7, cc = col & 127;
    float s = 0.f;
    for (int j = 0; j < 64; j++)
        s += poolp[(size_t)((b * 64 + j) * 4 + nt) * 128 + cc];
    xm[b * DMODEL + col] = s;
}

__global__ __launch_bounds__(512) void head_kernel(
    const float* __restrict__ xm, const float* __restrict__ Wc,
    const float* __restrict__ bc, float* __restrict__ out)
{
    int warp = threadIdx.x >> 5, lane = threadIdx.x & 31;
    int b = warp >> 1, cls = warp & 1;
    float s = 0.f;
    for (int d = lane; d < DMODEL; d += 32)
        s += xm[b * DMODEL + d] * Wc[d * NCLS + cls];
#pragma unroll
    for (int off = 16; off > 0; off >>= 1) s += __shfl_xor_sync(0xffffffffu, s, off);
    if (lane == 0) out[b * NCLS + cls] = s * (1.0f / SEQ) + bc[cls];
}

// ---------------- launch ----------------
#define SMEM_BN128_V (STAGES * (128 * 40 + 32 * 136) * 2)   // 75776
#define SMEM_BN64_V  (STAGES * (128 * 40 + 32 * 72) * 2)    // 59392

extern "C" void kernel_launch(void* const* d_in, const int* in_sizes, int n_in,
                              void* d_out, int out_size)
{
    (void)in_sizes; (void)n_in; (void)out_size;
    const int*   ids  = (const int*)  d_in[0];
    const float* emb  = (const float*)d_in[1];
    const float* Wq   = (const float*)d_in[2];
    const float* Wk   = (const float*)d_in[3];
    const float* Wv   = (const float*)d_in[4];
    const float* Wphi = (const float*)d_in[5];
    const float* Wo   = (const float*)d_in[6];
    const float* g1   = (const float*)d_in[7];
    const float* g2   = (const float*)d_in[8];
    const float* Wg   = (const float*)d_in[9];
    const float* Wu   = (const float*)d_in[10];
    const float* Wd   = (const float*)d_in[11];
    const float* Wc   = (const float*)d_in[12];
    const float* bc   = (const float*)d_in[13];
    float* out = (float*)d_out;

    float *kvp, *zp, *z, *poolp, *xm;
    __half *x, *h, *qkv, *pqk, *att, *gu, *kvh;
    __half *WqkvH, *WphiH, *WoH, *WguH, *WdH;
    cudaGetSymbolAddress((void**)&x,    g_x);
    cudaGetSymbolAddress((void**)&h,    g_h);
    cudaGetSymbolAddress((void**)&qkv,  g_qkv);
    cudaGetSymbolAddress((void**)&pqk,  g_pqk);
    cudaGetSymbolAddress((void**)&att,  g_att);
    cudaGetSymbolAddress((void**)&gu,   g_gu);
    cudaGetSymbolAddress((void**)&kvp,  g_kvp);
    cudaGetSymbolAddress((void**)&zp,   g_zp);
    cudaGetSymbolAddress((void**)&kvh,  g_kvh);
    cudaGetSymbolAddress((void**)&z,    g_z);
    cudaGetSymbolAddress((void**)&poolp, g_poolp);
    cudaGetSymbolAddress((void**)&xm,   g_xm);
    cudaGetSymbolAddress((void**)&WqkvH, g_WqkvH);
    cudaGetSymbolAddress((void**)&WphiH, g_WphiH);
    cudaGetSymbolAddress((void**)&WoH,   g_WoH);
    cudaGetSymbolAddress((void**)&WguH,  g_WguH);
    cudaGetSymbolAddress((void**)&WdH,   g_WdH);

    cudaFuncSetAttribute(gemm_h<128, EPI_QKV>,     cudaFuncAttributeMaxDynamicSharedMemorySize, SMEM_BN128_V);
    cudaFuncSetAttribute(gemm_h<128, EPI_RES>,     cudaFuncAttributeMaxDynamicSharedMemorySize, SMEM_BN128_V);
    cudaFuncSetAttribute(gemm_h<128, EPI_RESPOOL>, cudaFuncAttributeMaxDynamicSharedMemorySize, SMEM_BN128_V);
    cudaFuncSetAttribute(gemm_h<128, EPI_SWIGLU>,  cudaFuncAttributeMaxDynamicSharedMemorySize, SMEM_BN128_V);
    cudaFuncSetAttribute(gemm_h<64,  EPI_EXPABS>,  cudaFuncAttributeMaxDynamicSharedMemorySize, SMEM_BN64_V);

    // 1. merged weight conversion
    conv_all<<<(CTOT + 255) / 256, 256>>>(Wq, Wk, Wv, Wg, Wu, Wphi, Wo, Wd,
                                          WqkvH, WguH, WphiH, WoH, WdH);

    // 2. embedding gather + rmsnorm (x fp16)
    gather_rmsnorm_kernel<<<NTOK, 128>>>(ids, emb, nullptr, g1, x, h);

    // 3. fused qkv projection
    {
        dim3 grid(768 / 128, NTOK / 128);
        gemm_h<128, EPI_QKV><<<grid, NTHR, SMEM_BN128_V>>>(h, WqkvH, qkv, nullptr, NTOK, DMODEL, 768);
    }

    // 4. single Laplacian feature-map GEMM over q-rows + k-rows
    {
        dim3 grid(1, NTOK * (NHEAD + NKV) / 128);
        gemm_h<64, EPI_EXPABS><<<grid, NTHR, SMEM_BN64_V>>>(
            qkv, WphiH, pqk, nullptr, NTOK * (NHEAD + NKV), DHEAD, MFEAT);
    }

    // 5. tensor-core kv partials + reduce
    {
        dim3 gp(BATCH * NKV, KCH2);
        kv_partial_tc<<<gp, 128>>>(pqk + (size_t)NTOK * NHEAD * MFEAT,
                                   qkv + (size_t)NTOK * 640, kvp, zp);
        dim3 gr(BATCH * NKV, 4);
        kv_reduce_kernel<<<gr, 256>>>(kvp, zp, kvh, z);
    }

    // 6. tensor-core num + fp32 den -> attn
    {
        dim3 gn(NTOK / 128, NHEAD);
        numden_tc_kernel<<<gn, 128>>>(pqk, kvh, z, att);
    }

    // 7. output projection + residual (fp16 x)
    {
        dim3 grid(DMODEL / 128, NTOK / 128);
        gemm_h<128, EPI_RES><<<grid, NTHR, SMEM_BN128_V>>>(att, WoH, x, x, NTOK, DMODEL, DMODEL);
    }

    // 8. pre-FFN rmsnorm (reads fp16 x)
    gather_rmsnorm_kernel<<<NTOK, 128>>>(nullptr, nullptr, x, g2, nullptr, h);

    // 9. fused SwiGLU up
    {
        dim3 grid(4096 / 128, NTOK / 128);
        gemm_h<128, EPI_SWIGLU><<<grid, NTHR, SMEM_BN128_V>>>(h, WguH, gu, nullptr, NTOK, DMODEL, 4096);
    }
    // 10. down proj + residual, pooled in-epilogue (no x write)
    {
        dim3 grid(DMODEL / 128, NTOK / 128);
        gemm_h<128, EPI_RESPOOL><<<grid, NTHR, SMEM_BN128_V>>>(gu, WdH, poolp, x, NTOK, DFF, DMODEL);
    }

    // 11. pool partial reduce + head
    poolred_kernel<<<BATCH, 512>>>(poolp, xm);
    head_kernel<<<1, 512>>>(xm, Wc, bc, out);
}

// round 17
// speedup vs baseline: 1.4800x; 1.0009x over previous
#include <cuda_runtime.h>
#include <cuda_fp16.h>
#include <cuda_pipeline.h>
#include <mma.h>
#include <math.h>
#include <cstdint>

using namespace nvcuda;

// ---------------- problem constants ----------------
#define NTOK   65536
#define BATCH  8
#define SEQ    8192
#define DMODEL 512
#define NHEAD  8
#define NKV    2
#define DHEAD  64
#define MFEAT  64
#define DFF    2048
#define NCLS   2
#define EPSV   1e-6f
#define KCH2   16          // kv chunks of 512 tokens

// ---------------- scratch ----------------
__device__ __half g_x   [NTOK * DMODEL];          // fp16 residual stream
__device__ __half g_h   [NTOK * DMODEL];
__device__ __half g_qkv [NTOK * (DMODEL + 2*128)];   // q | k | v contiguous
__device__ __half g_pqk [NTOK * (NHEAD + NKV) * MFEAT];
__device__ __half g_att [NTOK * DMODEL];
__device__ __half g_gu  [NTOK * DFF];
__device__ float  g_kvp [16 * KCH2 * 64 * 64];
__device__ float  g_zp  [16 * KCH2 * 64];
__device__ __half g_kvh [16 * 64 * 64];
__device__ float  g_z   [16 * 64];
__device__ float  g_poolp[512 * 4 * 128];         // per (mtile, ntile) col sums
__device__ float  g_xm  [BATCH * DMODEL];
// converted fp16 weights, row-major [K, N]
__device__ __half g_WqkvH[DMODEL * 768];
__device__ __half g_WphiH[DHEAD * MFEAT];
__device__ __half g_WoH  [DMODEL * DMODEL];
__device__ __half g_WguH [DMODEL * (2*DFF)];
__device__ __half g_WdH  [DFF * DMODEL];

struct alignas(8) half4 { __half2 a, b; };
__device__ __forceinline__ half4 f4_to_h4(float4 v) {
    half4 r; r.a = __floats2half2_rn(v.x, v.y); r.b = __floats2half2_rn(v.z, v.w); return r;
}

// ---------------- single merged weight conversion ----------------
#define CQKV 393216
#define CGU  2097152
#define CPHI 4096
#define CWO  262144
#define CWD  1048576
#define CTOT (CQKV + CGU + CPHI + CWO + CWD)

__global__ void conv_all(const float* __restrict__ Wq, const float* __restrict__ Wk,
                         const float* __restrict__ Wv, const float* __restrict__ Wg,
                         const float* __restrict__ Wu, const float* __restrict__ Wphi,
                         const float* __restrict__ Wo, const float* __restrict__ Wd,
                         __half* __restrict__ WqkvH, __half* __restrict__ WguH,
                         __half* __restrict__ WphiH, __half* __restrict__ WoH,
                         __half* __restrict__ WdH)
{
    int idx = blockIdx.x * 256 + threadIdx.x;
    if (idx < CQKV) {
        int r = idx / 768, c = idx % 768;
        float v = (c < 512) ? Wq[r * 512 + c]
                            : (c < 640 ? Wk[r * 128 + c - 512] : Wv[r * 128 + c - 640]);
        WqkvH[idx] = __float2half(v);
        return;
    }
    idx -= CQKV;
    if (idx < CGU) {
        int r = idx >> 12, c = idx & 4095;
        int j = c >> 1;
        float v = (c & 1) ? Wu[r * DFF + j] : Wg[r * DFF + j];
        WguH[idx] = __float2half(v);
        return;
    }
    idx -= CGU;
    if (idx < CPHI) { WphiH[idx] = __float2half(Wphi[idx]); return; }
    idx -= CPHI;
    if (idx < CWO)  { WoH[idx]   = __float2half(Wo[idx]);   return; }
    idx -= CWO;
    if (idx < CWD)  { WdH[idx]   = __float2half(Wd[idx]);   return; }
}

// ---------------- fp16 WMMA GEMM: 128 thr, 64x64 warp tile, 4 stages ----------------
#define EPI_QKV     0
#define EPI_EXPABS  1
#define EPI_RES     2
#define EPI_SWIGLU  3
#define EPI_RESPOOL 4
#define STAGES 4
#define NTHR   128

template<int BN, int EPI>
__global__ __launch_bounds__(NTHR, 3) void gemm_h(
    const __half* __restrict__ A, const __half* __restrict__ B,
    void* __restrict__ Cout, const __half* __restrict__ X,
    int M, int K, int Nc)
{
    constexpr int BM = 128, BK = 32;
    constexpr int LDA_S = BK + 8;
    constexpr int LDB_S = BN + 8;
    constexpr int LDC_S = BN + 4;
    constexpr int MI = 4;
    constexpr int NJ = BN / 32;
    constexpr int A_ELE = BM * LDA_S;
    constexpr int B_ELE = BK * LDB_S;
    constexpr int STG_ELE = A_ELE + B_ELE;

    extern __shared__ __align__(16) char smem_raw[];
    __half* stg = (__half*)smem_raw;

    const int tid  = threadIdx.x;
    const int bm   = blockIdx.y * BM;
    const int bn   = blockIdx.x * BN;
    const int warp = tid >> 5;
    const int wm   = (warp & 1) * 64;
    const int wn   = (warp >> 1) * (BN / 2);

    wmma::fragment<wmma::accumulator, 16, 16, 16, float> c[MI][NJ];
#pragma unroll
    for (int i = 0; i < MI; i++)
#pragma unroll
        for (int j = 0; j < NJ; j++) wmma::fill_fragment(c[i][j], 0.0f);

    const int nK = K / BK;

    auto load_stage = [&](int kt, int s) {
        __half* As = stg + s * STG_ELE;
        __half* Bs = As + A_ELE;
#pragma unroll
        for (int i = 0; i < 4; i++) {
            int idx = tid + i * NTHR;
            int r  = idx >> 2;
            int cc = (idx & 3) * 8;
            __pipeline_memcpy_async(&As[r * LDA_S + cc],
                                    &A[(size_t)(bm + r) * K + kt + cc], 16);
        }
        constexpr int CH = BN / 8;
        constexpr int NB = (BK * CH) / NTHR;
#pragma unroll
        for (int i = 0; i < NB; i++) {
            int idx = tid + i * NTHR;
            int r  = idx / CH;
            int cc = (idx % CH) * 8;
            __pipeline_memcpy_async(&Bs[r * LDB_S + cc],
                                    &B[(size_t)(kt + r) * Nc + bn + cc], 16);
        }
    };

#pragma unroll
    for (int s = 0; s < STAGES - 1; s++) {
        if (s < nK) load_stage(s * BK, s);
        __pipeline_commit();
    }

    for (int kt_i = 0; kt_i < nK; kt_i++) {
        __pipeline_wait_prior(STAGES - 2);
        __syncthreads();
        int ldk = kt_i + STAGES - 1;
        if (ldk < nK) load_stage(ldk * BK, ldk % STAGES);
        __pipeline_commit();

        int s = kt_i % STAGES;
        __half* As = stg + s * STG_ELE;
        __half* Bs = As + A_ELE;
#pragma unroll
        for (int kk = 0; kk < BK; kk += 16) {
            wmma::fragment<wmma::matrix_a, 16, 16, 16, __half, wmma::row_major> a[MI];
            wmma::fragment<wmma::matrix_b, 16, 16, 16, __half, wmma::row_major> b[NJ];
#pragma unroll
            for (int i = 0; i < MI; i++)
                wmma::load_matrix_sync(a[i], &As[(wm + i * 16) * LDA_S + kk], LDA_S);
#pragma unroll
            for (int j = 0; j < NJ; j++)
                wmma::load_matrix_sync(b[j], &Bs[kk * LDB_S + wn + j * 16], LDB_S);
#pragma unroll
            for (int i = 0; i < MI; i++)
#pragma unroll
                for (int j = 0; j < NJ; j++)
                    wmma::mma_sync(c[i][j], a[i], b[j], c[i][j]);
        }
    }

    // ---- epilogue ----
    if (EPI == EPI_SWIGLU || EPI == EPI_RES || EPI == EPI_RESPOOL) {
        __syncthreads();
        float* Cs = (float*)smem_raw;
        float* SP = (float*)(smem_raw + 64 * LDC_S * 4);
        constexpr int F4R = BN / 4;
        constexpr int NIT = (64 * F4R) / NTHR;
        float psum[4] = {0.f, 0.f, 0.f, 0.f};
#pragma unroll
        for (int hrow = 0; hrow < 2; hrow++) {
            __syncthreads();
            if ((wm >> 6) == hrow) {
#pragma unroll
                for (int i = 0; i < MI; i++)
#pragma unroll
                    for (int j = 0; j < NJ; j++)
                        wmma::store_matrix_sync(&Cs[((wm & 63) + i * 16) * LDC_S + wn + j * 16],
                                                c[i][j], LDC_S, wmma::mem_row_major);
            }
            __syncthreads();
#pragma unroll
            for (int i = 0; i < NIT; i++) {
                int e  = tid + i * NTHR;
                int r  = e / F4R;
                int cc = (e % F4R) * 4;
                float4 vv = *(float4*)&Cs[r * LDC_S + cc];
                int grow = bm + hrow * 64 + r;
                if (EPI == EPI_RES || EPI == EPI_RESPOOL) {
                    size_t gidx = (size_t)grow * Nc + bn + cc;
                    half4 xh = *(const half4*)&X[gidx];
                    float2 x0 = __half22float2(xh.a);
                    float2 x1 = __half22float2(xh.b);
                    vv.x += x0.x; vv.y += x0.y; vv.z += x1.x; vv.w += x1.y;
                    if (EPI == EPI_RES) {
                        *(half4*)&((__half*)Cout)[gidx] = f4_to_h4(vv);
                    } else {
                        psum[0] += vv.x; psum[1] += vv.y;
                        psum[2] += vv.z; psum[3] += vv.w;
                    }
                } else {
                    float s0 = vv.x / (1.0f + expf(-vv.x)) * vv.y;
                    float s1 = vv.z / (1.0f + expf(-vv.z)) * vv.w;
                    int jo = (bn + cc) >> 1;
                    *(__half2*)&((__half*)Cout)[(size_t)grow * (Nc >> 1) + jo] =
                        __floats2half2_rn(s0, s1);
                }
            }
        }
        if (EPI == EPI_RESPOOL) {
            int grp = tid / F4R, col4 = tid % F4R;
            __syncthreads();
#pragma unroll
            for (int k = 0; k < 4; k++) SP[grp * BN + col4 * 4 + k] = psum[k];
            __syncthreads();
            if (tid < BN) {
                float s = SP[tid] + SP[BN + tid] + SP[2 * BN + tid] + SP[3 * BN + tid];
                ((float*)Cout)[((size_t)blockIdx.y * gridDim.x + blockIdx.x) * BN + tid] = s;
            }
        }
    } else {
        // fragment-direct epilogues (QKV / EXPABS)
#pragma unroll
        for (int i = 0; i < MI; i++) {
#pragma unroll
            for (int j = 0; j < NJ; j++) {
                int grow = bm + wm + i * 16;
                int gcol = bn + wn + j * 16;
                wmma::fragment<wmma::accumulator, 16, 16, 16, __half> ch;
#pragma unroll
                for (int t = 0; t < ch.num_elements; t++) {
                    float v = c[i][j].x[t];
                    if (EPI == EPI_EXPABS) v = expf(-fabsf(v));
                    ch.x[t] = __float2half(v);
                }
                __half* dst; int ld, c0;
                if (EPI == EPI_QKV) {
                    if (gcol < 512)      { dst = (__half*)Cout;                    ld = 512; c0 = gcol; }
                    else if (gcol < 640) { dst = (__half*)Cout + (size_t)M * 512;  ld = 128; c0 = gcol - 512; }
                    else                 { dst = (__half*)Cout + (size_t)M * 640;  ld = 128; c0 = gcol - 640; }
                } else {
                    dst = (__half*)Cout; ld = Nc; c0 = gcol;
                }
                wmma::store_matrix_sync(dst + (size_t)grow * ld + c0, ch, ld,
                                        wmma::mem_row_major);
            }
        }
    }
}

// ---------------- lightweight phi kernel: P = exp(-|A @ Wphi|), K=N=64 ----------------
// 128 thr, 8x 128-row tiles per block, Wphi staged once, 2-buffer cp.async pipeline.
#define PHI_TILES 8
__global__ __launch_bounds__(128, 4) void phi_kernel(
    const __half* __restrict__ A, const __half* __restrict__ W,
    __half* __restrict__ P)
{
    __shared__ __half Wp[64 * 72];
    __shared__ __half As[2][128 * 72];
    const int tid = threadIdx.x;
    const int w   = tid >> 5;
    const int wm  = w * 32;
    const size_t row0 = (size_t)blockIdx.x * (PHI_TILES * 128);

    // stage Wphi + first A tile (group 0)
#pragma unroll
    for (int i = 0; i < 4; i++) {
        int e = tid + i * 128;             // 512 chunks of 16B
        int r = e >> 3, c8 = (e & 7) * 8;
        __pipeline_memcpy_async(&Wp[r * 72 + c8], &W[r * 64 + c8], 16);
    }
    auto load_tile = [&](int t, int s) {
        const __half* Ab = A + (row0 + (size_t)t * 128) * 64;
#pragma unroll
        for (int i = 0; i < 8; i++) {
            int e = tid + i * 128;         // 1024 chunks of 16B
            int r = e >> 3, c8 = (e & 7) * 8;
            __pipeline_memcpy_async(&As[s][r * 72 + c8], &Ab[(size_t)r * 64 + c8], 16);
        }
    };
    load_tile(0, 0);
    __pipeline_commit();

    for (int t = 0; t < PHI_TILES; t++) {
        __pipeline_wait_prior(0);
        __syncthreads();                   // stage t ready; all warps past tile t-1
        if (t + 1 < PHI_TILES) {
            load_tile(t + 1, (t + 1) & 1); // writes the buffer freed by the trailing sync
            __pipeline_commit();
        }
        const __half* Asb = As[t & 1];

        wmma::fragment<wmma::accumulator, 16, 16, 16, float> c[2][4];
#pragma unroll
        for (int i = 0; i < 2; i++)
#pragma unroll
            for (int j = 0; j < 4; j++) wmma::fill_fragment(c[i][j], 0.0f);
#pragma unroll
        for (int kk = 0; kk < 64; kk += 16) {
            wmma::fragment<wmma::matrix_a, 16, 16, 16, __half, wmma::row_major> a[2];
            wmma::fragment<wmma::matrix_b, 16, 16, 16, __half, wmma::row_major> b[4];
#pragma unroll
            for (int i = 0; i < 2; i++)
                wmma::load_matrix_sync(a[i], &Asb[(wm + i * 16) * 72 + kk], 72);
#pragma unroll
            for (int j = 0; j < 4; j++)
                wmma::load_matrix_sync(b[j], &Wp[kk * 72 + j * 16], 72);
#pragma unroll
            for (int i = 0; i < 2; i++)
#pragma unroll
                for (int j = 0; j < 4; j++)
                    wmma::mma_sync(c[i][j], a[i], b[j], c[i][j]);
        }
        // fragment-direct exp(-|.|) store
#pragma unroll
        for (int i = 0; i < 2; i++) {
#pragma unroll
            for (int j = 0; j < 4; j++) {
                wmma::fragment<wmma::accumulator, 16, 16, 16, __half> ph;
#pragma unroll
                for (int e = 0; e < ph.num_elements; e++)
                    ph.x[e] = __float2half(expf(-fabsf(c[i][j].x[e])));
                size_t gr = row0 + (size_t)t * 128 + wm + i * 16;
                wmma::store_matrix_sync(P + gr * 64 + j * 16, ph, 64,
                                        wmma::mem_row_major);
            }
        }
        __syncthreads();                   // protect As[t&1] before t+2 overwrites it
    }
}

// ---------------- gather + rmsnorm (fp16 x) ----------------
__global__ __launch_bounds__(128) void gather_rmsnorm_kernel(
    const int* __restrict__ ids, const float* __restrict__ emb,
    const __half* __restrict__ xin, const float* __restrict__ g,
    __half* __restrict__ xout, __half* __restrict__ h)
{
    int token = blockIdx.x;
    int c = threadIdx.x * 4;
    float4 v;
    if (ids) {
        v = *(const float4*)&emb[(size_t)ids[token] * DMODEL + c];
    } else {
        half4 xh = *(const half4*)&xin[(size_t)token * DMODEL + c];
        float2 a = __half22float2(xh.a), b = __half22float2(xh.b);
        v.x = a.x; v.y = a.y; v.z = b.x; v.w = b.y;
    }
    float ss = v.x * v.x + v.y * v.y + v.z * v.z + v.w * v.w;
#pragma unroll
    for (int off = 16; off > 0; off >>= 1) ss += __shfl_xor_sync(0xffffffffu, ss, off);
    __shared__ float sred[4];
    int warp = threadIdx.x >> 5, lane = threadIdx.x & 31;
    if (lane == 0) sred[warp] = ss;
    __syncthreads();
    float tot = sred[0] + sred[1] + sred[2] + sred[3];
    float scale = rsqrtf(tot * (1.0f / DMODEL) + EPSV);
    float4 gv = *(const float4*)&g[c];
    float4 o;
    o.x = v.x * scale * gv.x; o.y = v.y * scale * gv.y;
    o.z = v.z * scale * gv.z; o.w = v.w * scale * gv.w;
    if (xout) *(half4*)&xout[(size_t)token * DMODEL + c] = f4_to_h4(v);
    *(half4*)&h[(size_t)token * DMODEL + c] = f4_to_h4(o);
}

// ---------------- tensor-core kv partials ----------------
__global__ __launch_bounds__(128) void kv_partial_tc(
    const __half* __restrict__ pk, const __half* __restrict__ v,
    float* __restrict__ kvp, float* __restrict__ zp)
{
    int pair = blockIdx.x, chunk = blockIdx.y;
    int b = pair >> 1, kh = pair & 1;
    const int tid = threadIdx.x, w = tid >> 5;
    const int wm = (w & 1) * 32, wn = (w >> 1) * 32;
    const size_t base = (size_t)(b * SEQ + chunk * 512) * 128 + kh * 64;
    const __half* Ap = pk + base;
    const __half* Bp = v  + base;

    wmma::fragment<wmma::accumulator, 16, 16, 16, float> c[2][2];
#pragma unroll
    for (int i = 0; i < 2; i++)
#pragma unroll
        for (int j = 0; j < 2; j++) wmma::fill_fragment(c[i][j], 0.0f);

    for (int k = 0; k < 512; k += 16) {
        wmma::fragment<wmma::matrix_a, 16, 16, 16, __half, wmma::col_major> a[2];
        wmma::fragment<wmma::matrix_b, 16, 16, 16, __half, wmma::row_major> bb[2];
#pragma unroll
        for (int i = 0; i < 2; i++)
            wmma::load_matrix_sync(a[i], Ap + (size_t)k * 128 + wm + i * 16, 128);
#pragma unroll
        for (int j = 0; j < 2; j++)
            wmma::load_matrix_sync(bb[j], Bp + (size_t)k * 128 + wn + j * 16, 128);
#pragma unroll
        for (int i = 0; i < 2; i++)
#pragma unroll
            for (int j = 0; j < 2; j++)
                wmma::mma_sync(c[i][j], a[i], bb[j], c[i][j]);
    }
    float* o = kvp + ((size_t)pair * KCH2 + chunk) * 4096;
#pragma unroll
    for (int i = 0; i < 2; i++)
#pragma unroll
        for (int j = 0; j < 2; j++)
            wmma::store_matrix_sync(o + (wm + i * 16) * 64 + wn + j * 16, c[i][j], 64,
                                    wmma::mem_row_major);
    __shared__ float zs[2][64];
    int m = tid & 63, hf = tid >> 6;
    float s = 0.f;
    for (int t = hf * 256; t < hf * 256 + 256; t++)
        s += __half2float(Ap[(size_t)t * 128 + m]);
    zs[hf][m] = s;
    __syncthreads();
    if (tid < 64)
        zp[(pair * KCH2 + chunk) * 64 + tid] = zs[0][tid] + zs[1][tid];
}

// ---------------- kv reduce -> fp16 kv_d + fp32 z ----------------
__global__ __launch_bounds__(256) void kv_reduce_kernel(
    const float* __restrict__ kvp, const float* __restrict__ zp,
    __half* __restrict__ kvh, float* __restrict__ z)
{
    int pair = blockIdx.x, seg = blockIdx.y;
    int lo = seg * 1024;
    for (int idx = lo + threadIdx.x; idx < lo + 1024; idx += 256) {
        float s = 0.f;
#pragma unroll
        for (int c = 0; c < KCH2; c++)
            s += kvp[((size_t)pair * KCH2 + c) * 4096 + idx];
        kvh[(size_t)pair * 4096 + idx] = __float2half(s);
    }
    if (seg == 0 && threadIdx.x < 64) {
        float s = 0.f;
#pragma unroll
        for (int c = 0; c < KCH2; c++)
            s += zp[(pair * KCH2 + c) * 64 + threadIdx.x];
        z[pair * 64 + threadIdx.x] = s;
    }
}

// ---------------- tensor-core num + fp32 den -> attn ----------------
__global__ __launch_bounds__(128) void numden_tc_kernel(
    const __half* __restrict__ pq, const __half* __restrict__ kvh,
    const float* __restrict__ zg, __half* __restrict__ att)
{
    __shared__ __half kvs[64 * 72];
    __shared__ float  zs[64];
    __shared__ float  Cs[128 * 68];

    const int tid  = threadIdx.x;
    const int h    = blockIdx.y;
    const int kh   = h >> 2;
    const int tok0 = blockIdx.x * 128;
    const int pair = (tok0 >> 13) * 2 + kh;

#pragma unroll
    for (int i = 0; i < 4; i++) {
        int e = tid + i * 128;
        int r = e >> 3, c8 = (e & 7) * 8;
        *(uint4*)&kvs[r * 72 + c8] = *(const uint4*)&kvh[(size_t)pair * 4096 + r * 64 + c8];
    }
    if (tid < 64) zs[tid] = zg[pair * 64 + tid];
    __syncthreads();

    const int warp = tid >> 5;
    wmma::fragment<wmma::accumulator, 16, 16, 16, float> c[2][4];
#pragma unroll
    for (int i = 0; i < 2; i++)
#pragma unroll
        for (int j = 0; j < 4; j++) wmma::fill_fragment(c[i][j], 0.0f);

    const __half* Abase = pq + (size_t)(tok0 + warp * 32) * 512 + h * 64;
#pragma unroll
    for (int kk = 0; kk < 64; kk += 16) {
        wmma::fragment<wmma::matrix_a, 16, 16, 16, __half, wmma::row_major> a[2];
        wmma::fragment<wmma::matrix_b, 16, 16, 16, __half, wmma::row_major> b[4];
#pragma unroll
        for (int i = 0; i < 2; i++)
            wmma::load_matrix_sync(a[i], Abase + (size_t)i * 16 * 512 + kk, 512);
#pragma unroll
        for (int j = 0; j < 4; j++)
            wmma::load_matrix_sync(b[j], &kvs[kk * 72 + j * 16], 72);
#pragma unroll
        for (int i = 0; i < 2; i++)
#pragma unroll
            for (int j = 0; j < 4; j++)
                wmma::mma_sync(c[i][j], a[i], b[j], c[i][j]);
    }
#pragma unroll
    for (int i = 0; i < 2; i++)
#pragma unroll
        for (int j = 0; j < 4; j++)
            wmma::store_matrix_sync(&Cs[(warp * 32 + i * 16) * 68 + j * 16],
                                    c[i][j], 68, wmma::mem_row_major);

    const __half* prow = pq + (size_t)(tok0 + tid) * 512 + h * 64;
    float den = 0.f;
#pragma unroll
    for (int m = 0; m < 64; m += 2) {
        float2 pf = __half22float2(*(const __half2*)(prow + m));
        den = fmaf(pf.x, zs[m], den);
        den = fmaf(pf.y, zs[m + 1], den);
    }
    __syncwarp();
    float rr = 1.0f / (den + EPSV);
    __half* orow = att + (size_t)(tok0 + tid) * 512 + h * 64;
#pragma unroll
    for (int d = 0; d < 64; d += 4) {
        float4 v = *(float4*)&Cs[tid * 68 + d];
        half4 hv;
        hv.a = __floats2half2_rn(v.x * rr, v.y * rr);
        hv.b = __floats2half2_rn(v.z * rr, v.w * rr);
        *(half4*)(orow + d) = hv;
    }
}

// ---------------- pool partial reduce + head ----------------
__global__ __launch_bounds__(512) void poolred_kernel(
    const float* __restrict__ poolp, float* __restrict__ xm)
{
    int b = blockIdx.x;
    int col = threadIdx.x;
    int nt = col >> 7, cc = col & 127;
    float s = 0.f;
    for (int j = 0; j < 64; j++)
        s += poolp[(size_t)((b * 64 + j) * 4 + nt) * 128 + cc];
    xm[b * DMODEL + col] = s;
}

__global__ __launch_bounds__(512) void head_kernel(
    const float* __restrict__ xm, const float* __restrict__ Wc,
    const float* __restrict__ bc, float* __restrict__ out)
{
    int warp = threadIdx.x >> 5, lane = threadIdx.x & 31;
    int b = warp >> 1, cls = warp & 1;
    float s = 0.f;
    for (int d = lane; d < DMODEL; d += 32)
        s += xm[b * DMODEL + d] * Wc[d * NCLS + cls];
#pragma unroll
    for (int off = 16; off > 0; off >>= 1) s += __shfl_xor_sync(0xffffffffu, s, off);
    if (lane == 0) out[b * NCLS + cls] = s * (1.0f / SEQ) + bc[cls];
}

// ---------------- launch ----------------
#define SMEM_BN128_V (STAGES * (128 * 40 + 32 * 136) * 2)   // 75776

extern "C" void kernel_launch(void* const* d_in, const int* in_sizes, int n_in,
                              void* d_out, int out_size)
{
    (void)in_sizes; (void)n_in; (void)out_size;
    const int*   ids  = (const int*)  d_in[0];
    const float* emb  = (const float*)d_in[1];
    const float* Wq   = (const float*)d_in[2];
    const float* Wk   = (const float*)d_in[3];
    const float* Wv   = (const float*)d_in[4];
    const float* Wphi = (const float*)d_in[5];
    const float* Wo   = (const float*)d_in[6];
    const float* g1   = (const float*)d_in[7];
    const float* g2   = (const float*)d_in[8];
    const float* Wg   = (const float*)d_in[9];
    const float* Wu   = (const float*)d_in[10];
    const float* Wd   = (const float*)d_in[11];
    const float* Wc   = (const float*)d_in[12];
    const float* bc   = (const float*)d_in[13];
    float* out = (float*)d_out;

    float *kvp, *zp, *z, *poolp, *xm;
    __half *x, *h, *qkv, *pqk, *att, *gu, *kvh;
    __half *WqkvH, *WphiH, *WoH, *WguH, *WdH;
    cudaGetSymbolAddress((void**)&x,    g_x);
    cudaGetSymbolAddress((void**)&h,    g_h);
    cudaGetSymbolAddress((void**)&qkv,  g_qkv);
    cudaGetSymbolAddress((void**)&pqk,  g_pqk);
    cudaGetSymbolAddress((void**)&att,  g_att);
    cudaGetSymbolAddress((void**)&gu,   g_gu);
    cudaGetSymbolAddress((void**)&kvp,  g_kvp);
    cudaGetSymbolAddress((void**)&zp,   g_zp);
    cudaGetSymbolAddress((void**)&kvh,  g_kvh);
    cudaGetSymbolAddress((void**)&z,    g_z);
    cudaGetSymbolAddress((void**)&poolp, g_poolp);
    cudaGetSymbolAddress((void**)&xm,   g_xm);
    cudaGetSymbolAddress((void**)&WqkvH, g_WqkvH);
    cudaGetSymbolAddress((void**)&WphiH, g_WphiH);
    cudaGetSymbolAddress((void**)&WoH,   g_WoH);
    cudaGetSymbolAddress((void**)&WguH,  g_WguH);
    cudaGetSymbolAddress((void**)&WdH,   g_WdH);

    cudaFuncSetAttribute(gemm_h<128, EPI_QKV>,     cudaFuncAttributeMaxDynamicSharedMemorySize, SMEM_BN128_V);
    cudaFuncSetAttribute(gemm_h<128, EPI_RES>,     cudaFuncAttributeMaxDynamicSharedMemorySize, SMEM_BN128_V);
    cudaFuncSetAttribute(gemm_h<128, EPI_RESPOOL>, cudaFuncAttributeMaxDynamicSharedMemorySize, SMEM_BN128_V);
    cudaFuncSetAttribute(gemm_h<128, EPI_SWIGLU>,  cudaFuncAttributeMaxDynamicSharedMemorySize, SMEM_BN128_V);

    // 1. merged weight conversion
    conv_all<<<(CTOT + 255) / 256, 256>>>(Wq, Wk, Wv, Wg, Wu, Wphi, Wo, Wd,
                                          WqkvH, WguH, WphiH, WoH, WdH);

    // 2. embedding gather + rmsnorm (x fp16)
    gather_rmsnorm_kernel<<<NTOK, 128>>>(ids, emb, nullptr, g1, x, h);

    // 3. fused qkv projection
    {
        dim3 grid(768 / 128, NTOK / 128);
        gemm_h<128, EPI_QKV><<<grid, NTHR, SMEM_BN128_V>>>(h, WqkvH, qkv, nullptr, NTOK, DMODEL, 768);
    }

    // 4. lightweight phi over q-rows + k-rows (contiguous, M = 655360)
    phi_kernel<<<NTOK * (NHEAD + NKV) / (PHI_TILES * 128), 128>>>(qkv, WphiH, pqk);

    // 5. tensor-core kv partials + reduce
    {
        dim3 gp(BATCH * NKV, KCH2);
        kv_partial_tc<<<gp, 128>>>(pqk + (size_t)NTOK * NHEAD * MFEAT,
                                   qkv + (size_t)NTOK * 640, kvp, zp);
        dim3 gr(BATCH * NKV, 4);
        kv_reduce_kernel<<<gr, 256>>>(kvp, zp, kvh, z);
    }

    // 6. tensor-core num + fp32 den -> attn
    {
        dim3 gn(NTOK / 128, NHEAD);
        numden_tc_kernel<<<gn, 128>>>(pqk, kvh, z, att);
    }

    // 7. output projection + residual (fp16 x)
    {
        dim3 grid(DMODEL / 128, NTOK / 128);
        gemm_h<128, EPI_RES><<<grid, NTHR, SMEM_BN128_V>>>(att, WoH, x, x, NTOK, DMODEL, DMODEL);
    }

    // 8. pre-FFN rmsnorm (reads fp16 x)
    gather_rmsnorm_kernel<<<NTOK, 128>>>(nullptr, nullptr, x, g2, nullptr, h);

    // 9. fused SwiGLU up
    {
        dim3 grid(4096 / 128, NTOK / 128);
        gemm_h<128, EPI_SWIGLU><<<grid, NTHR, SMEM_BN128_V>>>(h, WguH, gu, nullptr, NTOK, DMODEL, 4096);
    }
    // 10. down proj + residual, pooled in-epilogue (no x write)
    {
        dim3 grid(DMODEL / 128, NTOK / 128);
        gemm_h<128, EPI_RESPOOL><<<grid, NTHR, SMEM_BN128_V>>>(gu, WdH, poolp, x, NTOK, DFF, DMODEL);
    }

    // 11. pool partial reduce + head
    poolred_kernel<<<BATCH, 512>>>(poolp, xm);
    head_kernel<<<1, 512>>>(xm, Wc, bc, out);
}